// round 1
// baseline (speedup 1.0000x reference)
#include <cuda_runtime.h>
#include <math.h>

// ---------------- problem constants ----------------
#define NP 200000
#define NA 100000
#define NKW 50000
#define NN 350000            // total nodes
#define C 128
#define H 4
#define D 32
#define LAYERS 2
#define NR 4
#define E_TOT 600000
#define SRC_TOT (NA + 3*NP)  // 700000 (rel0 uses authors, rel1-3 use papers)

static const int E_SIZES_H[4]  = {150000, 150000, 200000, 100000};
static const int OFFS_H[3]     = {0, NP, NP + NA};
static const int REL_ST[4]     = {1, 0, 0, 0};
static const int REL_DT[4]     = {0, 1, 0, 2};
static const int KRELOFF_H[4]  = {0, NA, NA + NP, NA + 2*NP};
static const int EOFF_H[4]     = {0, 150000, 300000, 500000};
static const int NT_H[3]       = {NP, NA, NKW};

// ---------------- scratch (device globals; no allocation allowed) ----------------
__device__ float g_X   [(size_t)NN * C];
__device__ float g_KQV [(size_t)NN * 3 * C];
__device__ float g_Krel[(size_t)SRC_TOT * C];
__device__ float g_Vrel[(size_t)SRC_TOT * C];
__device__ float g_alpha[(size_t)E_TOT * H];
__device__ float g_ea   [(size_t)E_TOT * H];
__device__ float g_amax [(size_t)NN * H];
__device__ float g_denom[(size_t)NN * H];
__device__ float g_agg  [(size_t)NN * C];

// ---------------- helpers ----------------
__device__ __forceinline__ float gelu_f(float x) {
    return 0.5f * x * (1.0f + erff(x * 0.70710678118654752440f));
}

__device__ __forceinline__ void atomicMaxF(float* addr, float v) {
    if (v >= 0.f) atomicMax((int*)addr, __float_as_int(v));
    else          atomicMin((unsigned int*)addr, __float_as_uint(v));
}

// ---------------- generic M x 128 -> M x Ncols GEMM ----------------
// mode 0: relu(A@W + b)            (input linear)
// mode 1: A@W + b                  (kqv)
// mode 2: sg*(gelu(A)@W + b) + (1-sg)*Xold   (output proj + skip)
__global__ void gemm128(const float* __restrict__ Ain, const float* __restrict__ W,
                        const float* __restrict__ bias, float* __restrict__ Y,
                        const float* __restrict__ Xold, const float* __restrict__ skipPtr,
                        int M, int Ncols, int mode)
{
    __shared__ float As[16][72];   // [k][row], padded row stride (16B aligned)
    __shared__ float Ws[16][72];   // [k][col]

    const int tid = threadIdx.x;           // 256 threads
    const int tx = tid & 15, ty = tid >> 4;
    const int rowBase = blockIdx.x * 64;
    const int colBase = blockIdx.y * 64;

    float acc[4][4];
#pragma unroll
    for (int i = 0; i < 4; i++)
#pragma unroll
        for (int j = 0; j < 4; j++) acc[i][j] = 0.f;

    const int lr = tid >> 2;           // A tile row 0..63
    const int lc = (tid & 3) * 4;      // A k sub-col 0,4,8,12
    const int wr = tid >> 4;           // W tile k-row 0..15
    const int wc = (tid & 15) * 4;     // W col 0..60

    for (int k0 = 0; k0 < 128; k0 += 16) {
        float4 av = make_float4(0.f, 0.f, 0.f, 0.f);
        int arow = rowBase + lr;
        if (arow < M) av = *(const float4*)(Ain + (size_t)arow * 128 + k0 + lc);
        if (mode == 2) {
            av.x = gelu_f(av.x); av.y = gelu_f(av.y);
            av.z = gelu_f(av.z); av.w = gelu_f(av.w);
        }
        As[lc + 0][lr] = av.x; As[lc + 1][lr] = av.y;
        As[lc + 2][lr] = av.z; As[lc + 3][lr] = av.w;

        float4 wv = *(const float4*)(W + (size_t)(k0 + wr) * Ncols + colBase + wc);
        *(float4*)&Ws[wr][wc] = wv;

        __syncthreads();
#pragma unroll
        for (int kk = 0; kk < 16; kk++) {
            float4 a = *(const float4*)&As[kk][ty * 4];
            float4 b = *(const float4*)&Ws[kk][tx * 4];
            acc[0][0] += a.x * b.x; acc[0][1] += a.x * b.y; acc[0][2] += a.x * b.z; acc[0][3] += a.x * b.w;
            acc[1][0] += a.y * b.x; acc[1][1] += a.y * b.y; acc[1][2] += a.y * b.z; acc[1][3] += a.y * b.w;
            acc[2][0] += a.z * b.x; acc[2][1] += a.z * b.y; acc[2][2] += a.z * b.z; acc[2][3] += a.z * b.w;
            acc[3][0] += a.w * b.x; acc[3][1] += a.w * b.y; acc[3][2] += a.w * b.z; acc[3][3] += a.w * b.w;
        }
        __syncthreads();
    }

    float sg = 0.f;
    if (mode == 2) sg = 1.f / (1.f + expf(-*skipPtr));

    const int col = colBase + tx * 4;
    float4 bv = *(const float4*)&bias[col];
#pragma unroll
    for (int i = 0; i < 4; i++) {
        int row = rowBase + ty * 4 + i;
        if (row >= M) continue;
        float4 v;
        v.x = acc[i][0] + bv.x; v.y = acc[i][1] + bv.y;
        v.z = acc[i][2] + bv.z; v.w = acc[i][3] + bv.w;
        if (mode == 0) {
            v.x = fmaxf(v.x, 0.f); v.y = fmaxf(v.y, 0.f);
            v.z = fmaxf(v.z, 0.f); v.w = fmaxf(v.w, 0.f);
        } else if (mode == 2) {
            float4 xo = *(const float4*)(Xold + (size_t)row * 128 + col);
            float og = 1.f - sg;
            v.x = sg * v.x + og * xo.x; v.y = sg * v.y + og * xo.y;
            v.z = sg * v.z + og * xo.z; v.w = sg * v.w + og * xo.w;
        }
        *(float4*)(Y + (size_t)row * Ncols + col) = v;
    }
}

// ---------------- per-layer buffer init ----------------
__global__ void init_layer_buffers()
{
    size_t i = (size_t)blockIdx.x * blockDim.x + threadIdx.x;
    size_t stride = (size_t)gridDim.x * blockDim.x;
    for (size_t k = i; k < (size_t)NN * H; k += stride) {
        g_amax[k]  = -3.402823466e38f;
        g_denom[k] = 0.f;
    }
    for (size_t k = i; k < (size_t)NN * C; k += stride) g_agg[k] = 0.f;
}

// ---------------- node-level relation transform: Krel = k @ Wk, Vrel = v @ Wv ----------------
// one warp per node; W in smem; shfl broadcast of k/v along D
__global__ void rel_transform(const float* __restrict__ Wk, const float* __restrict__ Wv,
                              float* __restrict__ Kout, float* __restrict__ Vout,
                              const float* __restrict__ KQV,
                              int nNodes, int kqvNodeOff)
{
    __shared__ float sWk[H * D * D];   // 16 KB
    __shared__ float sWv[H * D * D];   // 16 KB
    for (int i = threadIdx.x; i < H * D * D; i += blockDim.x) {
        sWk[i] = Wk[i];
        sWv[i] = Wv[i];
    }
    __syncthreads();

    int gwarp = (blockIdx.x * blockDim.x + threadIdx.x) >> 5;
    int lane  = threadIdx.x & 31;
    if (gwarp >= nNodes) return;

    const float* kq = KQV + (size_t)(gwarp + kqvNodeOff) * 384;
    float ko[H], vo[H];
#pragma unroll
    for (int h = 0; h < H; h++) {
        float kd = kq[h * 32 + lane];          // k
        float vd = kq[256 + h * 32 + lane];    // v
        float ak = 0.f, av = 0.f;
        const float* wk = &sWk[h * 1024];
        const float* wv = &sWv[h * 1024];
#pragma unroll
        for (int d = 0; d < 32; d++) {
            float bk = __shfl_sync(0xffffffffu, kd, d);
            float bv = __shfl_sync(0xffffffffu, vd, d);
            ak += bk * wk[d * 32 + lane];
            av += bv * wv[d * 32 + lane];
        }
        ko[h] = ak; vo[h] = av;
    }
    float* Ko = Kout + (size_t)gwarp * 128;
    float* Vo = Vout + (size_t)gwarp * 128;
#pragma unroll
    for (int h = 0; h < H; h++) {
        Ko[h * 32 + lane] = ko[h];
        Vo[h * 32 + lane] = vo[h];
    }
}

// ---------------- edge pass 1: alpha + segment max ----------------
__global__ void edge_alpha(const int* __restrict__ src, const int* __restrict__ dst, int E,
                           const float* __restrict__ Krel, const float* __restrict__ KQV,
                           float* __restrict__ alphaOut, float* __restrict__ amax,
                           const float* __restrict__ prel, int dstOff)
{
    int e    = (blockIdx.x * blockDim.x + threadIdx.x) >> 5;
    int lane = threadIdx.x & 31;
    if (e >= E) return;

    int s  = src[e];
    int dg = dst[e] + dstOff;
    float4 kr = *(const float4*)(Krel + (size_t)s * 128 + lane * 4);
    float4 q  = *(const float4*)(KQV + (size_t)dg * 384 + 128 + lane * 4);
    float p = kr.x * q.x + kr.y * q.y + kr.z * q.z + kr.w * q.w;
    p += __shfl_xor_sync(0xffffffffu, p, 1);
    p += __shfl_xor_sync(0xffffffffu, p, 2);
    p += __shfl_xor_sync(0xffffffffu, p, 4);
    int h = lane >> 3;
    if ((lane & 7) == 0) {
        float a = p * prel[h] * 0.17677669529663687f;  // 1/sqrt(32)
        alphaOut[(size_t)e * H + h] = a;
        atomicMaxF(&amax[(size_t)dg * H + h], a);
    }
}

// ---------------- edge pass 2: ea = exp(alpha - max), denom += ea ----------------
__global__ void edge_ea(const int* __restrict__ dst, int E,
                        const float* __restrict__ alpha, float* __restrict__ ea,
                        const float* __restrict__ amax, float* __restrict__ denom,
                        int dstOff)
{
    int e = blockIdx.x * blockDim.x + threadIdx.x;
    if (e >= E) return;
    int dg = dst[e] + dstOff;
    float4 a = *(const float4*)(alpha + (size_t)e * H);
    float4 m = *(const float4*)(amax + (size_t)dg * H);
    float4 r;
    r.x = expf(a.x - m.x); r.y = expf(a.y - m.y);
    r.z = expf(a.z - m.z); r.w = expf(a.w - m.w);
    *(float4*)(ea + (size_t)e * H) = r;
    atomicAdd(&denom[(size_t)dg * H + 0], r.x);
    atomicAdd(&denom[(size_t)dg * H + 1], r.y);
    atomicAdd(&denom[(size_t)dg * H + 2], r.z);
    atomicAdd(&denom[(size_t)dg * H + 3], r.w);
}

// ---------------- edge pass 3: agg[dst] += (ea/denom) * Vrel[src] ----------------
__global__ void edge_scatter(const int* __restrict__ src, const int* __restrict__ dst, int E,
                             const float* __restrict__ Vrel, const float* __restrict__ ea,
                             const float* __restrict__ denom, float* __restrict__ agg,
                             int dstOff)
{
    int e    = (blockIdx.x * blockDim.x + threadIdx.x) >> 5;
    int lane = threadIdx.x & 31;
    if (e >= E) return;

    int s  = src[e];
    int dg = dst[e] + dstOff;
    int h  = lane >> 3;
    float wgt = ea[(size_t)e * H + h] / fmaxf(denom[(size_t)dg * H + h], 1e-16f);
    float4 v = *(const float4*)(Vrel + (size_t)s * 128 + lane * 4);
    float* o = agg + (size_t)dg * 128 + lane * 4;
    atomicAdd(o + 0, wgt * v.x);
    atomicAdd(o + 1, wgt * v.y);
    atomicAdd(o + 2, wgt * v.z);
    atomicAdd(o + 3, wgt * v.w);
}

// ---------------- host launch ----------------
extern "C" void kernel_launch(void* const* d_in, const int* in_sizes, int n_in,
                              void* d_out, int out_size)
{
    (void)in_sizes; (void)n_in; (void)out_size;

    const float* x_in[3] = {(const float*)d_in[0], (const float*)d_in[1], (const float*)d_in[2]};
    const int* esrc[4]; const int* edst[4];
    for (int r = 0; r < 4; r++) { esrc[r] = (const int*)d_in[3 + 2 * r]; edst[r] = (const int*)d_in[4 + 2 * r]; }
    const float* W_in  = (const float*)d_in[11];
    const float* b_in  = (const float*)d_in[12];
    const float* Wkqv  = (const float*)d_in[13];
    const float* bkqv  = (const float*)d_in[14];
    const float* Wk_rel = (const float*)d_in[15];
    const float* Wv_rel = (const float*)d_in[16];
    const float* p_rel  = (const float*)d_in[17];
    const float* Wout   = (const float*)d_in[18];
    const float* bout   = (const float*)d_in[19];
    const float* skip   = (const float*)d_in[20];
    float* out = (float*)d_out;

    float *X, *KQV, *Krel, *Vrel, *alpha, *ea, *amax, *denom, *agg;
    cudaGetSymbolAddress((void**)&X,     g_X);
    cudaGetSymbolAddress((void**)&KQV,   g_KQV);
    cudaGetSymbolAddress((void**)&Krel,  g_Krel);
    cudaGetSymbolAddress((void**)&Vrel,  g_Vrel);
    cudaGetSymbolAddress((void**)&alpha, g_alpha);
    cudaGetSymbolAddress((void**)&ea,    g_ea);
    cudaGetSymbolAddress((void**)&amax,  g_amax);
    cudaGetSymbolAddress((void**)&denom, g_denom);
    cudaGetSymbolAddress((void**)&agg,   g_agg);

    // input linear + relu
    for (int t = 0; t < 3; t++) {
        int M = NT_H[t];
        dim3 grid((M + 63) / 64, C / 64);
        gemm128<<<grid, 256>>>(x_in[t], W_in + (size_t)t * C * C, b_in + (size_t)t * C,
                               X + (size_t)OFFS_H[t] * C, nullptr, nullptr, M, C, 0);
    }

    for (int l = 0; l < LAYERS; l++) {
        init_layer_buffers<<<1024, 256>>>();

        // kqv projection per node type
        for (int t = 0; t < 3; t++) {
            int M = NT_H[t];
            dim3 grid((M + 63) / 64, (3 * C) / 64);
            gemm128<<<grid, 256>>>(X + (size_t)OFFS_H[t] * C,
                                   Wkqv + (size_t)(l * 3 + t) * C * 3 * C,
                                   bkqv + (size_t)(l * 3 + t) * 3 * C,
                                   KQV + (size_t)OFFS_H[t] * 3 * C,
                                   nullptr, nullptr, M, 3 * C, 1);
        }

        // node-level relation transforms (k@Wk_rel, v@Wv_rel)
        for (int r = 0; r < NR; r++) {
            int st = REL_ST[r];
            int nNodes = NT_H[st];
            int blocks = (nNodes + 7) / 8;
            rel_transform<<<blocks, 256>>>(Wk_rel + (size_t)(l * NR + r) * H * D * D,
                                           Wv_rel + (size_t)(l * NR + r) * H * D * D,
                                           Krel + (size_t)KRELOFF_H[r] * C,
                                           Vrel + (size_t)KRELOFF_H[r] * C,
                                           KQV, nNodes, OFFS_H[st]);
        }

        // edge pass 1: alpha + segment max
        for (int r = 0; r < NR; r++) {
            int E = E_SIZES_H[r];
            edge_alpha<<<(E + 7) / 8, 256>>>(esrc[r], edst[r], E,
                                             Krel + (size_t)KRELOFF_H[r] * C, KQV,
                                             alpha + (size_t)EOFF_H[r] * H, amax,
                                             p_rel + (size_t)(l * NR + r) * H,
                                             OFFS_H[REL_DT[r]]);
        }
        // edge pass 2: exp + denom
        for (int r = 0; r < NR; r++) {
            int E = E_SIZES_H[r];
            edge_ea<<<(E + 255) / 256, 256>>>(edst[r], E,
                                              alpha + (size_t)EOFF_H[r] * H,
                                              ea + (size_t)EOFF_H[r] * H,
                                              amax, denom, OFFS_H[REL_DT[r]]);
        }
        // edge pass 3: weighted scatter into agg
        for (int r = 0; r < NR; r++) {
            int E = E_SIZES_H[r];
            edge_scatter<<<(E + 7) / 8, 256>>>(esrc[r], edst[r], E,
                                               Vrel + (size_t)KRELOFF_H[r] * C,
                                               ea + (size_t)EOFF_H[r] * H,
                                               denom, agg, OFFS_H[REL_DT[r]]);
        }

        // output projection: sg*(gelu(agg)@Wout + bout) + (1-sg)*X
        for (int t = 0; t < 3; t++) {
            int M = NT_H[t];
            dim3 grid((M + 63) / 64, C / 64);
            float* Y = (l == LAYERS - 1) ? out + (size_t)OFFS_H[t] * C
                                         : X + (size_t)OFFS_H[t] * C;
            gemm128<<<grid, 256>>>(agg + (size_t)OFFS_H[t] * C,
                                   Wout + (size_t)(l * 3 + t) * C * C,
                                   bout + (size_t)(l * 3 + t) * C,
                                   Y,
                                   X + (size_t)OFFS_H[t] * C,
                                   skip + (size_t)(l * 3 + t),
                                   M, C, 2);
        }
    }
}

// round 3
// speedup vs baseline: 2.3848x; 2.3848x over previous
#include <cuda_runtime.h>
#include <cuda_bf16.h>
#include <math.h>
#include <stdint.h>

// ---------------- problem constants ----------------
#define NP 200000
#define NA 100000
#define NKW 50000
#define NN 350000
#define C 128
#define H 4
#define D 32
#define LAYERS 2
#define NR 4
#define E_TOT 600000
#define SRC_TOT 700000   // rel0: A(100k) srcs, rel1-3: P(200k) each

static const int E_SIZES_H[4]  = {150000, 150000, 200000, 100000};
static const int OFFS_H[3]     = {0, NP, NP + NA};
static const int REL_ST[4]     = {1, 0, 0, 0};
static const int REL_DT[4]     = {0, 1, 0, 2};
static const int KRELOFF_H[4]  = {0, NA, NA + NP, NA + 2*NP};
static const int EOFF_H[4]     = {0, 150000, 300000, 500000};
static const int NT_H[3]       = {NP, NA, NKW};

// ---------------- scratch ----------------
__device__ float g_X    [(size_t)NN * C];
__device__ float g_Q    [(size_t)NN * C];
__device__ float g_KV   [(size_t)SRC_TOT * 256];   // [Krel(128) | Vrel(128)] per (rel,node)
__device__ float g_alpha[(size_t)E_TOT * H];
__device__ float g_ea   [(size_t)E_TOT * H];
__device__ float g_amax [(size_t)NN * H];
__device__ float g_denom[(size_t)NN * H];
__device__ float g_agg  [(size_t)NN * C];
// bf16 hi/lo weight images (row-major [k][n]) + biases
__device__ unsigned char g_wimg[2031616];
__device__ float g_bias[3968];

// image offsets (bytes): N=128 image = 64KB (hi 32K + lo 32K); N=256 = 128KB
#define IMG_IN(t)     ((size_t)(t) * 65536)
#define IMG_Q(l,t)    ((size_t)(3 + (l)*3 + (t)) * 65536)
#define IMG_OUT(l,t)  ((size_t)(9 + (l)*3 + (t)) * 65536)
#define IMG_KV(l,r)   ((size_t)15 * 65536 + (size_t)((l)*4 + (r)) * 131072)
// bias offsets (floats)
#define B_IN(t)     ((t) * 128)
#define B_Q(l,t)    (384 + ((l)*3 + (t)) * 128)
#define B_OUT(l,t)  (1152 + ((l)*3 + (t)) * 128)
#define B_KV(l,r)   (1920 + ((l)*4 + (r)) * 256)

// ---------------- helpers ----------------
__device__ __forceinline__ uint32_t smem_to_u32(const void* p) {
    uint32_t a;
    asm("{ .reg .u64 t; cvta.to.shared.u64 t, %1; cvt.u32.u64 %0, t; }" : "=r"(a) : "l"(p));
    return a;
}
__device__ __forceinline__ float gelu_f(float x) {
    return 0.5f * x * (1.0f + erff(x * 0.70710678118654752440f));
}
__device__ __forceinline__ void atomicMaxF(float* addr, float v) {
    if (v >= 0.f) atomicMax((int*)addr, __float_as_int(v));
    else          atomicMin((unsigned int*)addr, __float_as_uint(v));
}

__device__ __forceinline__ void ldm_x4(uint32_t* r, uint32_t a) {
    asm volatile("ldmatrix.sync.aligned.m8n8.x4.shared.b16 {%0,%1,%2,%3}, [%4];"
                 : "=r"(r[0]), "=r"(r[1]), "=r"(r[2]), "=r"(r[3]) : "r"(a));
}
__device__ __forceinline__ void ldm_x4_t(uint32_t* r, uint32_t a) {
    asm volatile("ldmatrix.sync.aligned.m8n8.x4.trans.shared.b16 {%0,%1,%2,%3}, [%4];"
                 : "=r"(r[0]), "=r"(r[1]), "=r"(r[2]), "=r"(r[3]) : "r"(a));
}
__device__ __forceinline__ void mma_bf16(float* d, const uint32_t* a, const uint32_t* b) {
    asm volatile(
        "mma.sync.aligned.m16n8k16.row.col.f32.bf16.bf16.f32 "
        "{%0,%1,%2,%3}, {%4,%5,%6,%7}, {%8,%9}, {%0,%1,%2,%3};"
        : "+f"(d[0]), "+f"(d[1]), "+f"(d[2]), "+f"(d[3])
        : "r"(a[0]), "r"(a[1]), "r"(a[2]), "r"(a[3]), "r"(b[0]), "r"(b[1]));
}

// ---------------- weight prep: fp32 -> row-major bf16 hi/lo image ----------------
__global__ void prep_plain(const float* __restrict__ W, int ldW,
                           const float* __restrict__ bias,
                           unsigned char* __restrict__ img, float* __restrict__ bOut, int NC)
{
    int idx = blockIdx.x * blockDim.x + threadIdx.x;
    if (idx >= NC * 128) return;
    int n = idx % NC, k = idx / NC;
    float v = W[(size_t)k * ldW + n];
    uint32_t u = __float_as_uint(v);
    uint32_t hb = u & 0xFFFF0000u;
    float lo = v - __uint_as_float(hb);
    size_t off = ((size_t)k * NC + n) * 2;
    *(unsigned short*)(img + off) = (unsigned short)(hb >> 16);
    *(__nv_bfloat16*)(img + (size_t)NC * 256 + off) = __float2bfloat16(lo);
    if (k == 0) bOut[n] = bias[n];
}

// combined KV weights: Wc[k][n]; n<128 -> K-head transform, n>=128 -> V
__global__ void prep_kv(const float* __restrict__ Wkqv_t, const float* __restrict__ bkqv_t,
                        const float* __restrict__ Wk, const float* __restrict__ Wv,
                        unsigned char* __restrict__ img, float* __restrict__ bOut)
{
    int idx = blockIdx.x * blockDim.x + threadIdx.x;   // 256*128
    if (idx >= 256 * 128) return;
    int n = idx % 256, k = idx / 256;
    int isV = n >> 7, nn = n & 127, h = nn >> 5, f = nn & 31;
    const float* Wr = isV ? Wv : Wk;
    int kqvOff = isV ? 256 : 0;
    float v = 0.f;
#pragma unroll
    for (int d = 0; d < 32; d++)
        v += Wkqv_t[(size_t)k * 384 + kqvOff + h * 32 + d] * Wr[h * 1024 + d * 32 + f];
    uint32_t u = __float_as_uint(v);
    uint32_t hb = u & 0xFFFF0000u;
    float lo = v - __uint_as_float(hb);
    size_t off = ((size_t)k * 256 + n) * 2;
    *(unsigned short*)(img + off) = (unsigned short)(hb >> 16);
    *(__nv_bfloat16*)(img + 65536 + off) = __float2bfloat16(lo);
    if (k == 0) {
        float b = 0.f;
#pragma unroll
        for (int d = 0; d < 32; d++)
            b += bkqv_t[kqvOff + h * 32 + d] * Wr[h * 1024 + d * 32 + f];
        bOut[n] = b;
    }
}

// ---------------- HMMA GEMM: Y[:,colBase:colBase+128] = f(A[M,128]) @ W + bias ----------------
// MODE 0: relu(out)   MODE 1: out   MODE 2: gelu on A, blend with Xold via skip
// smem: A hi/lo + B hi/lo, each 128 rows x 272B padded stride (ldmatrix conflict-free)
template <int NC, int MODE>
__global__ void __launch_bounds__(256, 1) gemm_hmma(
    const float* __restrict__ Ain, const unsigned char* __restrict__ wimg,
    const float* __restrict__ bias, float* __restrict__ Y,
    const float* __restrict__ Xold, const float* __restrict__ skipPtr, int M)
{
    extern __shared__ char sm[];
    const int S = 272;                       // padded row stride (bytes)
    const int A_HI = 0, A_LO = 34816, B_HI = 69632, B_LO = 104448;

    const int tid = threadIdx.x, lane = tid & 31, w = tid >> 5;
    const int rowBase = blockIdx.x * 128, colBase = blockIdx.y * 128;
    const uint32_t smu = smem_to_u32(sm);

    // ---- B copy (hi image then lo image), 128 rows x 256B each ----
#pragma unroll
    for (int j = 0; j < 16; j++) {
        int idx = j * 256 + tid;             // 0..4095
        int im = idx >> 11;                  // 0=hi 1=lo
        int id = idx & 2047;
        int row = id >> 4, q = id & 15;
        uint4 v = *(const uint4*)(wimg + (size_t)im * NC * 256
                                  + ((size_t)row * NC + colBase) * 2 + q * 16);
        *(uint4*)(sm + (im ? B_LO : B_HI) + row * S + q * 16) = v;
    }

    // ---- A load + split-bf16 convert ----
#pragma unroll
    for (int j = 0; j < 16; j++) {
        int f = j * 256 + tid;               // 0..4095 float4s
        int row = f >> 5, col = (f & 31) * 4;
        float4 v = make_float4(0.f, 0.f, 0.f, 0.f);
        int gr = rowBase + row;
        if (gr < M) v = *(const float4*)(Ain + (size_t)gr * 128 + col);
        if (MODE == 2) {
            v.x = gelu_f(v.x); v.y = gelu_f(v.y); v.z = gelu_f(v.z); v.w = gelu_f(v.w);
        }
        uint32_t ux = __float_as_uint(v.x), uy = __float_as_uint(v.y);
        uint32_t uz = __float_as_uint(v.z), uw = __float_as_uint(v.w);
        uint32_t hi01 = __byte_perm(ux, uy, 0x7632);
        uint32_t hi23 = __byte_perm(uz, uw, 0x7632);
        float lx = v.x - __uint_as_float(ux & 0xFFFF0000u);
        float ly = v.y - __uint_as_float(uy & 0xFFFF0000u);
        float lz = v.z - __uint_as_float(uz & 0xFFFF0000u);
        float lw = v.w - __uint_as_float(uw & 0xFFFF0000u);
        uint32_t lo01, lo23;
        asm("cvt.rn.satfinite.bf16x2.f32 %0, %1, %2;" : "=r"(lo01) : "f"(ly), "f"(lx));
        asm("cvt.rn.satfinite.bf16x2.f32 %0, %1, %2;" : "=r"(lo23) : "f"(lw), "f"(lz));
        *(uint2*)(sm + A_HI + row * S + col * 2) = make_uint2(hi01, hi23);
        *(uint2*)(sm + A_LO + row * S + col * 2) = make_uint2(lo01, lo23);
    }
    __syncthreads();

    // ---- compute: warp (wm, wn) owns rows wm*32..+32, cols wn*64..+64 ----
    const int wm = w & 3, wn = w >> 2;
    const int lr = lane & 15, lc = lane >> 4;
    const uint32_t aHi = smu + A_HI + (wm * 32 + lr) * S + lc * 16;
    const uint32_t aLo = aHi + 34816;
    const uint32_t bHi = smu + B_HI + lr * S + (wn * 64 + lc * 8) * 2;
    const uint32_t bLo = bHi + 34816;

    float acc[2][8][4];
#pragma unroll
    for (int mi = 0; mi < 2; mi++)
#pragma unroll
        for (int nj = 0; nj < 8; nj++)
#pragma unroll
            for (int q = 0; q < 4; q++) acc[mi][nj][q] = 0.f;

#pragma unroll
    for (int ks = 0; ks < 8; ks++) {
        uint32_t ah[2][4], al[2][4], bh[4][4], bl[4][4];
        ldm_x4(ah[0], aHi + ks * 32);
        ldm_x4(ah[1], aHi + ks * 32 + 16 * S);
        ldm_x4(al[0], aLo + ks * 32);
        ldm_x4(al[1], aLo + ks * 32 + 16 * S);
#pragma unroll
        for (int nb = 0; nb < 4; nb++) {
            ldm_x4_t(bh[nb], bHi + ks * 16 * S + nb * 32);
            ldm_x4_t(bl[nb], bLo + ks * 16 * S + nb * 32);
        }
#pragma unroll
        for (int mi = 0; mi < 2; mi++)
#pragma unroll
            for (int nj = 0; nj < 8; nj++) {
                const uint32_t* bfh = &bh[nj >> 1][(nj & 1) * 2];
                const uint32_t* bfl = &bl[nj >> 1][(nj & 1) * 2];
                mma_bf16(acc[mi][nj], ah[mi], bfh);   // hi*hi
                mma_bf16(acc[mi][nj], ah[mi], bfl);   // hi*lo
                mma_bf16(acc[mi][nj], al[mi], bfh);   // lo*hi
            }
    }

    // ---- epilogue ----
    float sg = 0.f, og = 0.f;
    if (MODE == 2) { sg = 1.f / (1.f + expf(-*skipPtr)); og = 1.f - sg; }
    const int gid = lane >> 2, tc = (lane & 3) * 2;

#pragma unroll
    for (int mi = 0; mi < 2; mi++) {
#pragma unroll
        for (int nj = 0; nj < 8; nj++) {
            int col = colBase + wn * 64 + nj * 8 + tc;
            float b0 = __ldg(bias + col), b1 = __ldg(bias + col + 1);
#pragma unroll
            for (int half = 0; half < 2; half++) {
                int row = rowBase + wm * 32 + mi * 16 + gid + half * 8;
                if (row >= M) continue;
                float o0 = acc[mi][nj][half * 2 + 0] + b0;
                float o1 = acc[mi][nj][half * 2 + 1] + b1;
                if (MODE == 0) {
                    o0 = fmaxf(o0, 0.f); o1 = fmaxf(o1, 0.f);
                } else if (MODE == 2) {
                    float2 xo = *(const float2*)(Xold + (size_t)row * 128 + col);
                    o0 = sg * o0 + og * xo.x;
                    o1 = sg * o1 + og * xo.y;
                }
                *(float2*)(Y + (size_t)row * NC + col) = make_float2(o0, o1);
            }
        }
    }
}

// ---------------- per-layer buffer init ----------------
__global__ void init_layer_buffers()
{
    size_t i = (size_t)blockIdx.x * blockDim.x + threadIdx.x;
    size_t stride = (size_t)gridDim.x * blockDim.x;
    for (size_t k = i; k < (size_t)NN * H; k += stride) {
        g_amax[k]  = -3.402823466e38f;
        g_denom[k] = 0.f;
    }
    for (size_t k = i; k < (size_t)NN * C; k += stride) g_agg[k] = 0.f;
}

// ---------------- edge pass 1: alpha + segment max ----------------
__global__ void edge_alpha(const int* __restrict__ src, const int* __restrict__ dst, int E,
                           const float* __restrict__ KV, const float* __restrict__ Q,
                           float* __restrict__ alphaOut, float* __restrict__ amax,
                           const float* __restrict__ prel, int dstOff)
{
    int e    = (blockIdx.x * blockDim.x + threadIdx.x) >> 5;
    int lane = threadIdx.x & 31;
    if (e >= E) return;
    int s  = src[e];
    int dg = dst[e] + dstOff;
    float4 kr = *(const float4*)(KV + (size_t)s * 256 + lane * 4);
    float4 q  = *(const float4*)(Q + (size_t)dg * 128 + lane * 4);
    float p = kr.x * q.x + kr.y * q.y + kr.z * q.z + kr.w * q.w;
    p += __shfl_xor_sync(0xffffffffu, p, 1);
    p += __shfl_xor_sync(0xffffffffu, p, 2);
    p += __shfl_xor_sync(0xffffffffu, p, 4);
    int h = lane >> 3;
    if ((lane & 7) == 0) {
        float a = p * prel[h] * 0.17677669529663687f;  // 1/sqrt(32)
        alphaOut[(size_t)e * H + h] = a;
        atomicMaxF(&amax[(size_t)dg * H + h], a);
    }
}

// ---------------- edge pass 2: ea = exp(alpha - max), denom += ea ----------------
__global__ void edge_ea(const int* __restrict__ dst, int E,
                        const float* __restrict__ alpha, float* __restrict__ ea,
                        const float* __restrict__ amax, float* __restrict__ denom, int dstOff)
{
    int e = blockIdx.x * blockDim.x + threadIdx.x;
    if (e >= E) return;
    int dg = dst[e] + dstOff;
    float4 a = *(const float4*)(alpha + (size_t)e * H);
    float4 m = *(const float4*)(amax + (size_t)dg * H);
    float4 r;
    r.x = expf(a.x - m.x); r.y = expf(a.y - m.y);
    r.z = expf(a.z - m.z); r.w = expf(a.w - m.w);
    *(float4*)(ea + (size_t)e * H) = r;
    atomicAdd(&denom[(size_t)dg * H + 0], r.x);
    atomicAdd(&denom[(size_t)dg * H + 1], r.y);
    atomicAdd(&denom[(size_t)dg * H + 2], r.z);
    atomicAdd(&denom[(size_t)dg * H + 3], r.w);
}

// ---------------- edge pass 3: agg[dst] += (ea/denom) * Vrel[src] ----------------
__global__ void edge_scatter(const int* __restrict__ src, const int* __restrict__ dst, int E,
                             const float* __restrict__ KV, const float* __restrict__ ea,
                             const float* __restrict__ denom, float* __restrict__ agg, int dstOff)
{
    int e    = (blockIdx.x * blockDim.x + threadIdx.x) >> 5;
    int lane = threadIdx.x & 31;
    if (e >= E) return;
    int s  = src[e];
    int dg = dst[e] + dstOff;
    int h  = lane >> 3;
    float wgt = ea[(size_t)e * H + h] / fmaxf(denom[(size_t)dg * H + h], 1e-16f);
    float4 v = *(const float4*)(KV + (size_t)s * 256 + 128 + lane * 4);
    float* o = agg + (size_t)dg * 128 + lane * 4;
    atomicAdd(o + 0, wgt * v.x);
    atomicAdd(o + 1, wgt * v.y);
    atomicAdd(o + 2, wgt * v.z);
    atomicAdd(o + 3, wgt * v.w);
}

// ---------------- host launch ----------------
extern "C" void kernel_launch(void* const* d_in, const int* in_sizes, int n_in,
                              void* d_out, int out_size)
{
    (void)in_sizes; (void)n_in; (void)out_size;

    const float* x_in[3] = {(const float*)d_in[0], (const float*)d_in[1], (const float*)d_in[2]};
    const int* esrc[4]; const int* edst[4];
    for (int r = 0; r < 4; r++) { esrc[r] = (const int*)d_in[3 + 2*r]; edst[r] = (const int*)d_in[4 + 2*r]; }
    const float* W_in   = (const float*)d_in[11];
    const float* b_in   = (const float*)d_in[12];
    const float* Wkqv   = (const float*)d_in[13];
    const float* bkqv   = (const float*)d_in[14];
    const float* Wk_rel = (const float*)d_in[15];
    const float* Wv_rel = (const float*)d_in[16];
    const float* p_rel  = (const float*)d_in[17];
    const float* Wout   = (const float*)d_in[18];
    const float* bout   = (const float*)d_in[19];
    const float* skip   = (const float*)d_in[20];
    float* out = (float*)d_out;

    float *X, *Q, *KV, *alpha, *ea, *amax, *denom, *agg, *bias;
    unsigned char* wimg;
    cudaGetSymbolAddress((void**)&X,     g_X);
    cudaGetSymbolAddress((void**)&Q,     g_Q);
    cudaGetSymbolAddress((void**)&KV,    g_KV);
    cudaGetSymbolAddress((void**)&alpha, g_alpha);
    cudaGetSymbolAddress((void**)&ea,    g_ea);
    cudaGetSymbolAddress((void**)&amax,  g_amax);
    cudaGetSymbolAddress((void**)&denom, g_denom);
    cudaGetSymbolAddress((void**)&agg,   g_agg);
    cudaGetSymbolAddress((void**)&wimg,  g_wimg);
    cudaGetSymbolAddress((void**)&bias,  g_bias);

    const int SMEM = 139264;   // 4 x (128 rows x 272B)
    cudaFuncSetAttribute(gemm_hmma<128,0>, cudaFuncAttributeMaxDynamicSharedMemorySize, SMEM);
    cudaFuncSetAttribute(gemm_hmma<128,1>, cudaFuncAttributeMaxDynamicSharedMemorySize, SMEM);
    cudaFuncSetAttribute(gemm_hmma<128,2>, cudaFuncAttributeMaxDynamicSharedMemorySize, SMEM);
    cudaFuncSetAttribute(gemm_hmma<256,1>, cudaFuncAttributeMaxDynamicSharedMemorySize, SMEM);

    // ---- weight prep (all layers up-front) ----
    for (int t = 0; t < 3; t++)
        prep_plain<<<(128*128 + 255)/256, 256>>>(W_in + (size_t)t*C*C, 128, b_in + t*128,
                                                 wimg + IMG_IN(t), bias + B_IN(t), 128);
    for (int l = 0; l < LAYERS; l++) {
        for (int t = 0; t < 3; t++) {
            prep_plain<<<(128*128 + 255)/256, 256>>>(
                Wkqv + (size_t)(l*3 + t)*C*384 + 128, 384, bkqv + (size_t)(l*3 + t)*384 + 128,
                wimg + IMG_Q(l,t), bias + B_Q(l,t), 128);
            prep_plain<<<(128*128 + 255)/256, 256>>>(
                Wout + (size_t)(l*3 + t)*C*C, 128, bout + (size_t)(l*3 + t)*128,
                wimg + IMG_OUT(l,t), bias + B_OUT(l,t), 128);
        }
        for (int r = 0; r < NR; r++) {
            int st = REL_ST[r];
            prep_kv<<<(256*128 + 255)/256, 256>>>(
                Wkqv + (size_t)(l*3 + st)*C*384, bkqv + (size_t)(l*3 + st)*384,
                Wk_rel + (size_t)(l*NR + r)*4096, Wv_rel + (size_t)(l*NR + r)*4096,
                wimg + IMG_KV(l,r), bias + B_KV(l,r));
        }
    }

    // ---- input linear + relu ----
    for (int t = 0; t < 3; t++) {
        int M = NT_H[t];
        dim3 grid((M + 127)/128, 1);
        gemm_hmma<128,0><<<grid, 256, SMEM>>>(
            x_in[t], wimg + IMG_IN(t), bias + B_IN(t),
            X + (size_t)OFFS_H[t]*C, nullptr, nullptr, M);
    }

    for (int l = 0; l < LAYERS; l++) {
        init_layer_buffers<<<1024, 256>>>();

        // Q projection per type
        for (int t = 0; t < 3; t++) {
            int M = NT_H[t];
            dim3 grid((M + 127)/128, 1);
            gemm_hmma<128,1><<<grid, 256, SMEM>>>(
                X + (size_t)OFFS_H[t]*C, wimg + IMG_Q(l,t), bias + B_Q(l,t),
                Q + (size_t)OFFS_H[t]*C, nullptr, nullptr, M);
        }
        // combined Krel|Vrel per relation
        for (int r = 0; r < NR; r++) {
            int st = REL_ST[r];
            int M = NT_H[st];
            dim3 grid((M + 127)/128, 2);
            gemm_hmma<256,1><<<grid, 256, SMEM>>>(
                X + (size_t)OFFS_H[st]*C, wimg + IMG_KV(l,r), bias + B_KV(l,r),
                KV + (size_t)KRELOFF_H[r]*256, nullptr, nullptr, M);
        }

        // edges
        for (int r = 0; r < NR; r++) {
            int E = E_SIZES_H[r];
            edge_alpha<<<(E + 7)/8, 256>>>(esrc[r], edst[r], E,
                                           KV + (size_t)KRELOFF_H[r]*256, Q,
                                           alpha + (size_t)EOFF_H[r]*H, amax,
                                           p_rel + (size_t)(l*NR + r)*H, OFFS_H[REL_DT[r]]);
        }
        for (int r = 0; r < NR; r++) {
            int E = E_SIZES_H[r];
            edge_ea<<<(E + 255)/256, 256>>>(edst[r], E,
                                            alpha + (size_t)EOFF_H[r]*H, ea + (size_t)EOFF_H[r]*H,
                                            amax, denom, OFFS_H[REL_DT[r]]);
        }
        for (int r = 0; r < NR; r++) {
            int E = E_SIZES_H[r];
            edge_scatter<<<(E + 7)/8, 256>>>(esrc[r], edst[r], E,
                                             KV + (size_t)KRELOFF_H[r]*256, ea + (size_t)EOFF_H[r]*H,
                                             denom, agg, OFFS_H[REL_DT[r]]);
        }

        // output projection + skip
        for (int t = 0; t < 3; t++) {
            int M = NT_H[t];
            float* Y = (l == LAYERS - 1) ? out + (size_t)OFFS_H[t]*C
                                         : X + (size_t)OFFS_H[t]*C;
            dim3 grid((M + 127)/128, 1);
            gemm_hmma<128,2><<<grid, 256, SMEM>>>(
                agg + (size_t)OFFS_H[t]*C, wimg + IMG_OUT(l,t), bias + B_OUT(l,t),
                Y, X + (size_t)OFFS_H[t]*C, skip + (size_t)(l*3 + t), M);
        }
    }
}

// round 4
// speedup vs baseline: 2.5142x; 1.0543x over previous
#include <cuda_runtime.h>
#include <cuda_bf16.h>
#include <math.h>
#include <stdint.h>

// ---------------- problem constants ----------------
#define NP 200000
#define NA 100000
#define NKW 50000
#define NN 350000
#define C 128
#define H 4
#define D 32
#define LAYERS 2
#define NR 4
#define E_TOT 600000
#define SRC_TOT 700000   // rel0: A(100k) srcs, rel1-3: P(200k) each

static const int OFFS_H[3]     = {0, NP, NP + NA};
static const int REL_ST[4]     = {1, 0, 0, 0};
static const int KRELOFF_H[4]  = {0, NA, NA + NP, NA + 2*NP};
static const int NT_H[3]       = {NP, NA, NKW};

// ---------------- scratch ----------------
__device__ float g_X    [(size_t)NN * C];
__device__ float g_Q    [(size_t)NN * C];
__device__ float g_KV   [(size_t)SRC_TOT * 256];   // [Krel(128) | Vrel(128)] per (rel,node)
__device__ float g_denom[(size_t)NN * H];
__device__ float g_agg  [(size_t)NN * C];
// bf16 hi/lo weight images (row-major [k][n]) + biases
__device__ unsigned char g_wimg[2031616];
__device__ float g_bias[3968];

// image offsets (bytes): N=128 image = 64KB (hi 32K + lo 32K); N=256 = 128KB
#define IMG_IN(t)     ((size_t)(t) * 65536)
#define IMG_Q(l,t)    ((size_t)(3 + (l)*3 + (t)) * 65536)
#define IMG_OUT(l,t)  ((size_t)(9 + (l)*3 + (t)) * 65536)
#define IMG_KV(l,r)   ((size_t)15 * 65536 + (size_t)((l)*4 + (r)) * 131072)
// bias offsets (floats)
#define B_IN(t)     ((t) * 128)
#define B_Q(l,t)    (384 + ((l)*3 + (t)) * 128)
#define B_OUT(l,t)  (1152 + ((l)*3 + (t)) * 128)
#define B_KV(l,r)   (1920 + ((l)*4 + (r)) * 256)

// ---------------- helpers ----------------
__device__ __forceinline__ uint32_t smem_to_u32(const void* p) {
    uint32_t a;
    asm("{ .reg .u64 t; cvta.to.shared.u64 t, %1; cvt.u32.u64 %0, t; }" : "=r"(a) : "l"(p));
    return a;
}
__device__ __forceinline__ float gelu_f(float x) {
    return 0.5f * x * (1.0f + erff(x * 0.70710678118654752440f));
}
__device__ __forceinline__ void ldm_x4(uint32_t* r, uint32_t a) {
    asm volatile("ldmatrix.sync.aligned.m8n8.x4.shared.b16 {%0,%1,%2,%3}, [%4];"
                 : "=r"(r[0]), "=r"(r[1]), "=r"(r[2]), "=r"(r[3]) : "r"(a));
}
__device__ __forceinline__ void ldm_x4_t(uint32_t* r, uint32_t a) {
    asm volatile("ldmatrix.sync.aligned.m8n8.x4.trans.shared.b16 {%0,%1,%2,%3}, [%4];"
                 : "=r"(r[0]), "=r"(r[1]), "=r"(r[2]), "=r"(r[3]) : "r"(a));
}
__device__ __forceinline__ void mma_bf16(float* d, const uint32_t* a, const uint32_t* b) {
    asm volatile(
        "mma.sync.aligned.m16n8k16.row.col.f32.bf16.bf16.f32 "
        "{%0,%1,%2,%3}, {%4,%5,%6,%7}, {%8,%9}, {%0,%1,%2,%3};"
        : "+f"(d[0]), "+f"(d[1]), "+f"(d[2]), "+f"(d[3])
        : "r"(a[0]), "r"(a[1]), "r"(a[2]), "r"(a[3]), "r"(b[0]), "r"(b[1]));
}

// ---------------- weight prep: fp32 -> row-major bf16 hi/lo image ----------------
__global__ void prep_plain(const float* __restrict__ W, int ldW,
                           const float* __restrict__ bias,
                           unsigned char* __restrict__ img, float* __restrict__ bOut, int NC)
{
    int idx = blockIdx.x * blockDim.x + threadIdx.x;
    if (idx >= NC * 128) return;
    int n = idx % NC, k = idx / NC;
    float v = W[(size_t)k * ldW + n];
    uint32_t u = __float_as_uint(v);
    uint32_t hb = u & 0xFFFF0000u;
    float lo = v - __uint_as_float(hb);
    size_t off = ((size_t)k * NC + n) * 2;
    *(unsigned short*)(img + off) = (unsigned short)(hb >> 16);
    *(__nv_bfloat16*)(img + (size_t)NC * 256 + off) = __float2bfloat16(lo);
    if (k == 0) bOut[n] = bias[n];
}

// combined KV weights: Wc[k][n]; n<128 -> K-head transform, n>=128 -> V
__global__ void prep_kv(const float* __restrict__ Wkqv_t, const float* __restrict__ bkqv_t,
                        const float* __restrict__ Wk, const float* __restrict__ Wv,
                        unsigned char* __restrict__ img, float* __restrict__ bOut)
{
    int idx = blockIdx.x * blockDim.x + threadIdx.x;   // 256*128
    if (idx >= 256 * 128) return;
    int n = idx % 256, k = idx / 256;
    int isV = n >> 7, nn = n & 127, h = nn >> 5, f = nn & 31;
    const float* Wr = isV ? Wv : Wk;
    int kqvOff = isV ? 256 : 0;
    float v = 0.f;
#pragma unroll
    for (int d = 0; d < 32; d++)
        v += Wkqv_t[(size_t)k * 384 + kqvOff + h * 32 + d] * Wr[h * 1024 + d * 32 + f];
    uint32_t u = __float_as_uint(v);
    uint32_t hb = u & 0xFFFF0000u;
    float lo = v - __uint_as_float(hb);
    size_t off = ((size_t)k * 256 + n) * 2;
    *(unsigned short*)(img + off) = (unsigned short)(hb >> 16);
    *(__nv_bfloat16*)(img + 65536 + off) = __float2bfloat16(lo);
    if (k == 0) {
        float b = 0.f;
#pragma unroll
        for (int d = 0; d < 32; d++)
            b += bkqv_t[kqvOff + h * 32 + d] * Wr[h * 1024 + d * 32 + f];
        bOut[n] = b;
    }
}

// ---------------- HMMA GEMM: Y[:,colBase:+128] = f(A[M,128]) @ W + bias ----------------
// 64-row tiles, 2 CTAs/SM. MODE 0: relu  MODE 1: none  MODE 2: (A/denom)->gelu, skip blend
template <int NC, int MODE>
__global__ void __launch_bounds__(256, 2) gemm_hmma(
    const float* __restrict__ Ain, const unsigned char* __restrict__ wimg,
    const float* __restrict__ bias, float* __restrict__ Y,
    const float* __restrict__ Xold, const float* __restrict__ skipPtr,
    const float* __restrict__ denomPtr, int M)
{
    extern __shared__ char sm[];
    const int S = 272;                       // padded row stride (bytes)
    const int A_HI = 0, A_LO = 17408, B_HI = 34816, B_LO = 69632;

    const int tid = threadIdx.x, lane = tid & 31, w = tid >> 5;
    const int rowBase = blockIdx.x * 64, colBase = blockIdx.y * 128;
    const uint32_t smu = smem_to_u32(sm);

    // ---- B copy (hi then lo image), 128 k-rows x 256B each ----
#pragma unroll
    for (int j = 0; j < 16; j++) {
        int idx = j * 256 + tid;             // 0..4095 uint4
        int im = idx >> 11;                  // 0=hi 1=lo
        int id = idx & 2047;
        int row = id >> 4, q = id & 15;
        uint4 v = *(const uint4*)(wimg + (size_t)im * NC * 256
                                  + ((size_t)row * NC + colBase) * 2 + q * 16);
        *(uint4*)(sm + (im ? B_LO : B_HI) + row * S + q * 16) = v;
    }

    // ---- A load + (normalize/gelu) + split-bf16 convert ----
#pragma unroll
    for (int j = 0; j < 8; j++) {
        int f = j * 256 + tid;               // 0..2047 float4
        int row = f >> 5, col = (f & 31) * 4;
        float4 v = make_float4(0.f, 0.f, 0.f, 0.f);
        int gr = rowBase + row;
        if (gr < M) v = *(const float4*)(Ain + (size_t)gr * 128 + col);
        if (MODE == 2) {
            float inv = 1.f / fmaxf(denomPtr[(size_t)gr * 4 + (col >> 5)], 1e-16f);
            v.x = gelu_f(v.x * inv); v.y = gelu_f(v.y * inv);
            v.z = gelu_f(v.z * inv); v.w = gelu_f(v.w * inv);
        }
        uint32_t ux = __float_as_uint(v.x), uy = __float_as_uint(v.y);
        uint32_t uz = __float_as_uint(v.z), uw = __float_as_uint(v.w);
        uint32_t hi01 = __byte_perm(ux, uy, 0x7632);
        uint32_t hi23 = __byte_perm(uz, uw, 0x7632);
        float lx = v.x - __uint_as_float(ux & 0xFFFF0000u);
        float ly = v.y - __uint_as_float(uy & 0xFFFF0000u);
        float lz = v.z - __uint_as_float(uz & 0xFFFF0000u);
        float lw = v.w - __uint_as_float(uw & 0xFFFF0000u);
        uint32_t lo01, lo23;
        asm("cvt.rn.satfinite.bf16x2.f32 %0, %1, %2;" : "=r"(lo01) : "f"(ly), "f"(lx));
        asm("cvt.rn.satfinite.bf16x2.f32 %0, %1, %2;" : "=r"(lo23) : "f"(lw), "f"(lz));
        *(uint2*)(sm + A_HI + row * S + col * 2) = make_uint2(hi01, hi23);
        *(uint2*)(sm + A_LO + row * S + col * 2) = make_uint2(lo01, lo23);
    }
    __syncthreads();

    // ---- compute: warp (wm, wn): rows wm*16..+16, cols wn*64..+64 ----
    const int wm = w & 3, wn = w >> 2;
    const int lr = lane & 15, lc = lane >> 4;
    const uint32_t aHi = smu + A_HI + (wm * 16 + lr) * S + lc * 16;
    const uint32_t aLo = aHi + 17408;
    const uint32_t bHi = smu + B_HI + lr * S + (wn * 64 + lc * 8) * 2;
    const uint32_t bLo = bHi + 34816;

    float acc[8][4];
#pragma unroll
    for (int nj = 0; nj < 8; nj++)
#pragma unroll
        for (int q = 0; q < 4; q++) acc[nj][q] = 0.f;

#pragma unroll
    for (int ks = 0; ks < 8; ks++) {
        uint32_t ah[4], al[4], bh[4][4], bl[4][4];
        ldm_x4(ah, aHi + ks * 32);
        ldm_x4(al, aLo + ks * 32);
#pragma unroll
        for (int nb = 0; nb < 4; nb++) {
            ldm_x4_t(bh[nb], bHi + ks * 16 * S + nb * 32);
            ldm_x4_t(bl[nb], bLo + ks * 16 * S + nb * 32);
        }
#pragma unroll
        for (int nj = 0; nj < 8; nj++) {
            const uint32_t* bfh = &bh[nj >> 1][(nj & 1) * 2];
            const uint32_t* bfl = &bl[nj >> 1][(nj & 1) * 2];
            mma_bf16(acc[nj], ah, bfh);   // hi*hi
            mma_bf16(acc[nj], ah, bfl);   // hi*lo
            mma_bf16(acc[nj], al, bfh);   // lo*hi
        }
    }

    // ---- epilogue ----
    float sg = 0.f, og = 0.f;
    if (MODE == 2) { sg = 1.f / (1.f + expf(-*skipPtr)); og = 1.f - sg; }
    const int gid = lane >> 2, tc = (lane & 3) * 2;

#pragma unroll
    for (int nj = 0; nj < 8; nj++) {
        int col = colBase + wn * 64 + nj * 8 + tc;
        float b0 = __ldg(bias + col), b1 = __ldg(bias + col + 1);
#pragma unroll
        for (int half = 0; half < 2; half++) {
            int row = rowBase + wm * 16 + gid + half * 8;
            if (row >= M) continue;
            float o0 = acc[nj][half * 2 + 0] + b0;
            float o1 = acc[nj][half * 2 + 1] + b1;
            if (MODE == 0) {
                o0 = fmaxf(o0, 0.f); o1 = fmaxf(o1, 0.f);
            } else if (MODE == 2) {
                float2 xo = *(const float2*)(Xold + (size_t)row * 128 + col);
                o0 = sg * o0 + og * xo.x;
                o1 = sg * o1 + og * xo.y;
            }
            *(float2*)(Y + (size_t)row * NC + col) = make_float2(o0, o1);
        }
    }
}

// ---------------- per-layer buffer init ----------------
__global__ void init_layer_buffers()
{
    size_t i = (size_t)blockIdx.x * blockDim.x + threadIdx.x;
    size_t stride = (size_t)gridDim.x * blockDim.x;
    for (size_t k = i; k < (size_t)NN * H; k += stride) g_denom[k] = 0.f;
    float4 z = make_float4(0.f, 0.f, 0.f, 0.f);
    float4* agg4 = (float4*)g_agg;
    for (size_t k = i; k < (size_t)NN * 32; k += stride) agg4[k] = z;
}

// ---------------- fused edge pass: alpha -> exp -> denom & unnormalized scatter ----------------
__global__ void __launch_bounds__(256) edge_fused(
    const int* __restrict__ s0, const int* __restrict__ d0,
    const int* __restrict__ s1, const int* __restrict__ d1,
    const int* __restrict__ s2, const int* __restrict__ d2,
    const int* __restrict__ s3, const int* __restrict__ d3,
    const float* __restrict__ KV, const float* __restrict__ Q,
    const float* __restrict__ prel, float* __restrict__ denom, float* __restrict__ agg)
{
    int gw   = (blockIdx.x * blockDim.x + threadIdx.x) >> 5;
    int lane = threadIdx.x & 31;
    if (gw >= E_TOT) return;

    const int* sp; const int* dp; int kvoff, doff, r, e = gw;
    if (gw < 150000)      { r = 0; sp = s0; dp = d0; kvoff = 0;      doff = 0; }
    else if (gw < 300000) { r = 1; sp = s1; dp = d1; kvoff = 100000; doff = 200000; e -= 150000; }
    else if (gw < 500000) { r = 2; sp = s2; dp = d2; kvoff = 300000; doff = 0;      e -= 300000; }
    else                  { r = 3; sp = s3; dp = d3; kvoff = 500000; doff = 300000; e -= 500000; }

    int s  = sp[e] + kvoff;
    int dg = dp[e] + doff;
    const float* kvrow = KV + (size_t)s * 256;

    float4 kr = *(const float4*)(kvrow + lane * 4);
    float4 q  = *(const float4*)(Q + (size_t)dg * 128 + lane * 4);
    float p = kr.x * q.x + kr.y * q.y + kr.z * q.z + kr.w * q.w;
    p += __shfl_xor_sync(0xffffffffu, p, 1);
    p += __shfl_xor_sync(0xffffffffu, p, 2);
    p += __shfl_xor_sync(0xffffffffu, p, 4);   // all 8 lanes of a head now hold the dot
    int h = lane >> 3;
    float a  = p * prel[r * 4 + h] * 0.17677669529663687f;   // 1/sqrt(32)
    float ea = expf(a);
    if ((lane & 7) == 0) atomicAdd(denom + (size_t)dg * 4 + h, ea);

    float4 vv = *(const float4*)(kvrow + 128 + lane * 4);
    float* o = agg + (size_t)dg * 128 + lane * 4;
    atomicAdd(o + 0, ea * vv.x);
    atomicAdd(o + 1, ea * vv.y);
    atomicAdd(o + 2, ea * vv.z);
    atomicAdd(o + 3, ea * vv.w);
}

// ---------------- host launch ----------------
extern "C" void kernel_launch(void* const* d_in, const int* in_sizes, int n_in,
                              void* d_out, int out_size)
{
    (void)in_sizes; (void)n_in; (void)out_size;

    const float* x_in[3] = {(const float*)d_in[0], (const float*)d_in[1], (const float*)d_in[2]};
    const int* esrc[4]; const int* edst[4];
    for (int r = 0; r < 4; r++) { esrc[r] = (const int*)d_in[3 + 2*r]; edst[r] = (const int*)d_in[4 + 2*r]; }
    const float* W_in   = (const float*)d_in[11];
    const float* b_in   = (const float*)d_in[12];
    const float* Wkqv   = (const float*)d_in[13];
    const float* bkqv   = (const float*)d_in[14];
    const float* Wk_rel = (const float*)d_in[15];
    const float* Wv_rel = (const float*)d_in[16];
    const float* p_rel  = (const float*)d_in[17];
    const float* Wout   = (const float*)d_in[18];
    const float* bout   = (const float*)d_in[19];
    const float* skip   = (const float*)d_in[20];
    float* out = (float*)d_out;

    float *X, *Q, *KV, *denom, *agg, *bias;
    unsigned char* wimg;
    cudaGetSymbolAddress((void**)&X,     g_X);
    cudaGetSymbolAddress((void**)&Q,     g_Q);
    cudaGetSymbolAddress((void**)&KV,    g_KV);
    cudaGetSymbolAddress((void**)&denom, g_denom);
    cudaGetSymbolAddress((void**)&agg,   g_agg);
    cudaGetSymbolAddress((void**)&wimg,  g_wimg);
    cudaGetSymbolAddress((void**)&bias,  g_bias);

    const int SMEM = 104448;   // A 2x17408 + B 2x34816
    cudaFuncSetAttribute(gemm_hmma<128,0>, cudaFuncAttributeMaxDynamicSharedMemorySize, SMEM);
    cudaFuncSetAttribute(gemm_hmma<128,1>, cudaFuncAttributeMaxDynamicSharedMemorySize, SMEM);
    cudaFuncSetAttribute(gemm_hmma<128,2>, cudaFuncAttributeMaxDynamicSharedMemorySize, SMEM);
    cudaFuncSetAttribute(gemm_hmma<256,1>, cudaFuncAttributeMaxDynamicSharedMemorySize, SMEM);

    // ---- weight prep (all layers up-front) ----
    for (int t = 0; t < 3; t++)
        prep_plain<<<(128*128 + 255)/256, 256>>>(W_in + (size_t)t*C*C, 128, b_in + t*128,
                                                 wimg + IMG_IN(t), bias + B_IN(t), 128);
    for (int l = 0; l < LAYERS; l++) {
        for (int t = 0; t < 3; t++) {
            prep_plain<<<(128*128 + 255)/256, 256>>>(
                Wkqv + (size_t)(l*3 + t)*C*384 + 128, 384, bkqv + (size_t)(l*3 + t)*384 + 128,
                wimg + IMG_Q(l,t), bias + B_Q(l,t), 128);
            prep_plain<<<(128*128 + 255)/256, 256>>>(
                Wout + (size_t)(l*3 + t)*C*C, 128, bout + (size_t)(l*3 + t)*128,
                wimg + IMG_OUT(l,t), bias + B_OUT(l,t), 128);
        }
        for (int r = 0; r < NR; r++) {
            int st = REL_ST[r];
            prep_kv<<<(256*128 + 255)/256, 256>>>(
                Wkqv + (size_t)(l*3 + st)*C*384, bkqv + (size_t)(l*3 + st)*384,
                Wk_rel + (size_t)(l*NR + r)*4096, Wv_rel + (size_t)(l*NR + r)*4096,
                wimg + IMG_KV(l,r), bias + B_KV(l,r));
        }
    }

    // ---- input linear + relu ----
    for (int t = 0; t < 3; t++) {
        int M = NT_H[t];
        dim3 grid((M + 63)/64, 1);
        gemm_hmma<128,0><<<grid, 256, SMEM>>>(
            x_in[t], wimg + IMG_IN(t), bias + B_IN(t),
            X + (size_t)OFFS_H[t]*C, nullptr, nullptr, nullptr, M);
    }

    for (int l = 0; l < LAYERS; l++) {
        init_layer_buffers<<<1024, 256>>>();

        // Q projection per type
        for (int t = 0; t < 3; t++) {
            int M = NT_H[t];
            dim3 grid((M + 63)/64, 1);
            gemm_hmma<128,1><<<grid, 256, SMEM>>>(
                X + (size_t)OFFS_H[t]*C, wimg + IMG_Q(l,t), bias + B_Q(l,t),
                Q + (size_t)OFFS_H[t]*C, nullptr, nullptr, nullptr, M);
        }
        // combined Krel|Vrel per relation
        for (int r = 0; r < NR; r++) {
            int st = REL_ST[r];
            int M = NT_H[st];
            dim3 grid((M + 63)/64, 2);
            gemm_hmma<256,1><<<grid, 256, SMEM>>>(
                X + (size_t)OFFS_H[st]*C, wimg + IMG_KV(l,r), bias + B_KV(l,r),
                KV + (size_t)KRELOFF_H[r]*256, nullptr, nullptr, nullptr, M);
        }

        // fused edge pass (all 4 relations, one launch)
        edge_fused<<<(E_TOT * 32 + 255)/256, 256>>>(
            esrc[0], edst[0], esrc[1], edst[1], esrc[2], edst[2], esrc[3], edst[3],
            KV, Q, p_rel + (size_t)l*NR*H, denom, agg);

        // output projection + skip (normalize agg by denom inside A-load)
        for (int t = 0; t < 3; t++) {
            int M = NT_H[t];
            float* Y = (l == LAYERS - 1) ? out + (size_t)OFFS_H[t]*C
                                         : X + (size_t)OFFS_H[t]*C;
            dim3 grid((M + 63)/64, 1);
            gemm_hmma<128,2><<<grid, 256, SMEM>>>(
                agg + (size_t)OFFS_H[t]*C, wimg + IMG_OUT(l,t), bias + B_OUT(l,t),
                Y, X + (size_t)OFFS_H[t]*C, skip + (size_t)(l*3 + t),
                denom + (size_t)OFFS_H[t]*H, M);
        }
    }
}

// round 5
// speedup vs baseline: 2.8221x; 1.1225x over previous
#include <cuda_runtime.h>
#include <cuda_bf16.h>
#include <math.h>
#include <stdint.h>

// ---------------- problem constants ----------------
#define NP 200000
#define NA 100000
#define NKW 50000
#define NN 350000
#define C 128
#define H 4
#define D 32
#define LAYERS 2
#define NR 4
#define E_TOT 600000
#define SRC_TOT 700000   // rel0: A(100k) srcs, rel1-3: P(200k) each

static const int OFFS_H[3]     = {0, NP, NP + NA};
static const int KRELOFF_H[4]  = {0, NA, NA + NP, NA + 2*NP};
static const int NT_H[3]       = {NP, NA, NKW};

// ---------------- scratch ----------------
__device__ float g_X    [(size_t)NN * C];
__device__ float g_Q    [(size_t)NN * C];
__device__ float g_KV   [(size_t)SRC_TOT * 256];   // [Krel(128) | Vrel(128)] per (rel,node)
__device__ float g_denom[(size_t)NN * H];
__device__ float g_agg  [(size_t)NN * C];
__device__ unsigned char g_wimg[2031616];
__device__ float g_bias[3968];

#define IMG_IN(t)     ((size_t)(t) * 65536)
#define IMG_Q(l,t)    ((size_t)(3 + (l)*3 + (t)) * 65536)
#define IMG_OUT(l,t)  ((size_t)(9 + (l)*3 + (t)) * 65536)
#define IMG_KV(l,r)   ((size_t)15 * 65536 + (size_t)((l)*4 + (r)) * 131072)
#define B_IN(t)     ((t) * 128)
#define B_Q(l,t)    (384 + ((l)*3 + (t)) * 128)
#define B_OUT(l,t)  (1152 + ((l)*3 + (t)) * 128)
#define B_KV(l,r)   (1920 + ((l)*4 + (r)) * 256)

// ---------------- helpers ----------------
__device__ __forceinline__ uint32_t smem_to_u32(const void* p) {
    uint32_t a;
    asm("{ .reg .u64 t; cvta.to.shared.u64 t, %1; cvt.u32.u64 %0, t; }" : "=r"(a) : "l"(p));
    return a;
}
__device__ __forceinline__ float gelu_f(float x) {
    return 0.5f * x * (1.0f + erff(x * 0.70710678118654752440f));
}
__device__ __forceinline__ void ldm_x4(uint32_t* r, uint32_t a) {
    asm volatile("ldmatrix.sync.aligned.m8n8.x4.shared.b16 {%0,%1,%2,%3}, [%4];"
                 : "=r"(r[0]), "=r"(r[1]), "=r"(r[2]), "=r"(r[3]) : "r"(a));
}
__device__ __forceinline__ void ldm_x4_t(uint32_t* r, uint32_t a) {
    asm volatile("ldmatrix.sync.aligned.m8n8.x4.trans.shared.b16 {%0,%1,%2,%3}, [%4];"
                 : "=r"(r[0]), "=r"(r[1]), "=r"(r[2]), "=r"(r[3]) : "r"(a));
}
__device__ __forceinline__ void mma_bf16(float* d, const uint32_t* a, const uint32_t* b) {
    asm volatile(
        "mma.sync.aligned.m16n8k16.row.col.f32.bf16.bf16.f32 "
        "{%0,%1,%2,%3}, {%4,%5,%6,%7}, {%8,%9}, {%0,%1,%2,%3};"
        : "+f"(d[0]), "+f"(d[1]), "+f"(d[2]), "+f"(d[3])
        : "r"(a[0]), "r"(a[1]), "r"(a[2]), "r"(a[3]), "r"(b[0]), "r"(b[1]));
}

// ---------------- batched weight prep ----------------
struct PPlain { const float* W; long ldW; const float* bias; unsigned char* img; float* bOut; };
struct PPlainList { PPlain p[15]; };

__global__ void prep_plain_all(PPlainList L)
{
    const PPlain pp = L.p[blockIdx.y];
    int idx = blockIdx.x * blockDim.x + threadIdx.x;   // 0..16383
    int n = idx & 127, k = idx >> 7;
    float v = pp.W[(size_t)k * pp.ldW + n];
    uint32_t u = __float_as_uint(v);
    uint32_t hb = u & 0xFFFF0000u;
    float lo = v - __uint_as_float(hb);
    size_t off = ((size_t)k * 128 + n) * 2;
    *(unsigned short*)(pp.img + off) = (unsigned short)(hb >> 16);
    *(__nv_bfloat16*)(pp.img + 32768 + off) = __float2bfloat16(lo);
    if (k == 0) pp.bOut[n] = pp.bias[n];
}

struct PKV { const float* Wkqv; const float* bkqv; const float* Wk; const float* Wv;
             unsigned char* img; float* bOut; };
struct PKVList { PKV p[8]; };

__global__ void prep_kv_all(PKVList L)
{
    const PKV pp = L.p[blockIdx.y];
    int idx = blockIdx.x * blockDim.x + threadIdx.x;   // 0..32767
    int n = idx & 255, k = idx >> 8;
    int isV = n >> 7, nn = n & 127, h = nn >> 5, f = nn & 31;
    const float* Wr = isV ? pp.Wv : pp.Wk;
    int kqvOff = isV ? 256 : 0;
    float v = 0.f;
#pragma unroll
    for (int d = 0; d < 32; d++)
        v += pp.Wkqv[(size_t)k * 384 + kqvOff + h * 32 + d] * Wr[h * 1024 + d * 32 + f];
    uint32_t u = __float_as_uint(v);
    uint32_t hb = u & 0xFFFF0000u;
    float lo = v - __uint_as_float(hb);
    size_t off = ((size_t)k * 256 + n) * 2;
    *(unsigned short*)(pp.img + off) = (unsigned short)(hb >> 16);
    *(__nv_bfloat16*)(pp.img + 65536 + off) = __float2bfloat16(lo);
    if (k == 0) {
        float b = 0.f;
#pragma unroll
        for (int d = 0; d < 32; d++)
            b += pp.bkqv[kqvOff + h * 32 + d] * Wr[h * 1024 + d * 32 + f];
        pp.bOut[n] = b;
    }
}

// ---------------- multi-tile HMMA GEMM ----------------
// A (64 rows x 128) loaded into smem ONCE; loop over output col tiles.
// MODE 0: relu(out)  MODE 1: none  MODE 2: (A/denom)->gelu on load, skip blend on store
struct Tile {
    const unsigned char* img;   // bf16 hi image base (lo at +imgNC*256)
    const float* bias;          // 128 floats for this tile
    float* out;                 // output base (already column-offset)
    int imgNC;                  // image row width in cols (128 or 256)
    int colBase;                // column offset within image
    int stride;                 // output row stride (floats)
};
struct TileList { Tile t[7]; int n; };

template <int MODE>
__global__ void __launch_bounds__(256, 2) gemm_multi(
    const float* __restrict__ Ain, TileList tl,
    const float* __restrict__ Xold, const float* __restrict__ skipPtr,
    const float* __restrict__ denomPtr, int M)
{
    extern __shared__ char sm[];
    const int S = 272;
    const int A_HI = 0, A_LO = 17408, B_HI = 34816, B_LO = 69632;

    const int tid = threadIdx.x, lane = tid & 31, w = tid >> 5;
    const int rowBase = blockIdx.x * 64;
    const uint32_t smu = smem_to_u32(sm);

    // ---- A load + (normalize/gelu) + split-bf16 convert (once) ----
#pragma unroll
    for (int j = 0; j < 8; j++) {
        int f = j * 256 + tid;               // 0..2047 float4
        int row = f >> 5, col = (f & 31) * 4;
        float4 v = make_float4(0.f, 0.f, 0.f, 0.f);
        int gr = rowBase + row;
        if (gr < M) v = *(const float4*)(Ain + (size_t)gr * 128 + col);
        if (MODE == 2) {
            float inv = 1.f / fmaxf(denomPtr[(size_t)gr * 4 + (col >> 5)], 1e-16f);
            v.x = gelu_f(v.x * inv); v.y = gelu_f(v.y * inv);
            v.z = gelu_f(v.z * inv); v.w = gelu_f(v.w * inv);
        }
        uint32_t ux = __float_as_uint(v.x), uy = __float_as_uint(v.y);
        uint32_t uz = __float_as_uint(v.z), uw = __float_as_uint(v.w);
        uint32_t hi01 = __byte_perm(ux, uy, 0x7632);
        uint32_t hi23 = __byte_perm(uz, uw, 0x7632);
        float lx = v.x - __uint_as_float(ux & 0xFFFF0000u);
        float ly = v.y - __uint_as_float(uy & 0xFFFF0000u);
        float lz = v.z - __uint_as_float(uz & 0xFFFF0000u);
        float lw = v.w - __uint_as_float(uw & 0xFFFF0000u);
        uint32_t lo01, lo23;
        asm("cvt.rn.satfinite.bf16x2.f32 %0, %1, %2;" : "=r"(lo01) : "f"(ly), "f"(lx));
        asm("cvt.rn.satfinite.bf16x2.f32 %0, %1, %2;" : "=r"(lo23) : "f"(lw), "f"(lz));
        *(uint2*)(sm + A_HI + row * S + col * 2) = make_uint2(hi01, hi23);
        *(uint2*)(sm + A_LO + row * S + col * 2) = make_uint2(lo01, lo23);
    }

    float sg = 0.f, og = 0.f;
    if (MODE == 2) { sg = 1.f / (1.f + expf(-*skipPtr)); og = 1.f - sg; }

    const int wm = w & 3, wn = w >> 2;
    const int lr = lane & 15, lc = lane >> 4;
    const uint32_t aHi = smu + A_HI + (wm * 16 + lr) * S + lc * 16;
    const uint32_t aLo = aHi + 17408;
    const uint32_t bHiBase = smu + B_HI + lr * S + (wn * 64 + lc * 8) * 2;
    const int gid = lane >> 2, tc = (lane & 3) * 2;

    for (int ti = 0; ti < tl.n; ti++) {
        const Tile tile = tl.t[ti];

        // ---- B tile load (hi then lo), 128 k-rows x 256B each ----
#pragma unroll
        for (int j = 0; j < 16; j++) {
            int idx = j * 256 + tid;             // 0..4095 uint4
            int im = idx >> 11;                  // 0=hi 1=lo
            int id = idx & 2047;
            int row = id >> 4, q = id & 15;
            const unsigned char* base = tile.img + (size_t)im * tile.imgNC * 256;
            uint4 v = *(const uint4*)(base + ((size_t)row * tile.imgNC + tile.colBase) * 2 + q * 16);
            *(uint4*)(sm + (im ? B_LO : B_HI) + row * S + q * 16) = v;
        }
        __syncthreads();

        float acc[8][4];
#pragma unroll
        for (int nj = 0; nj < 8; nj++)
#pragma unroll
            for (int q = 0; q < 4; q++) acc[nj][q] = 0.f;

#pragma unroll
        for (int ks = 0; ks < 8; ks++) {
            uint32_t ah[4], al[4], bh[4][4], bl[4][4];
            ldm_x4(ah, aHi + ks * 32);
            ldm_x4(al, aLo + ks * 32);
#pragma unroll
            for (int nb = 0; nb < 4; nb++) {
                ldm_x4_t(bh[nb], bHiBase + ks * 16 * S + nb * 32);
                ldm_x4_t(bl[nb], bHiBase + 34816 + ks * 16 * S + nb * 32);
            }
#pragma unroll
            for (int nj = 0; nj < 8; nj++) {
                const uint32_t* bfh = &bh[nj >> 1][(nj & 1) * 2];
                const uint32_t* bfl = &bl[nj >> 1][(nj & 1) * 2];
                mma_bf16(acc[nj], ah, bfh);
                mma_bf16(acc[nj], ah, bfl);
                mma_bf16(acc[nj], al, bfh);
            }
        }

        // ---- epilogue ----
#pragma unroll
        for (int nj = 0; nj < 8; nj++) {
            int col = wn * 64 + nj * 8 + tc;
            float b0 = __ldg(tile.bias + col), b1 = __ldg(tile.bias + col + 1);
#pragma unroll
            for (int half = 0; half < 2; half++) {
                int row = rowBase + wm * 16 + gid + half * 8;
                if (row >= M) continue;
                float o0 = acc[nj][half * 2 + 0] + b0;
                float o1 = acc[nj][half * 2 + 1] + b1;
                if (MODE == 0) {
                    o0 = fmaxf(o0, 0.f); o1 = fmaxf(o1, 0.f);
                } else if (MODE == 2) {
                    float2 xo = *(const float2*)(Xold + (size_t)row * 128 + col);
                    o0 = sg * o0 + og * xo.x;
                    o1 = sg * o1 + og * xo.y;
                }
                *(float2*)(tile.out + (size_t)row * tile.stride + col) = make_float2(o0, o1);
            }
        }
        __syncthreads();   // B buffer reuse guard
    }
}

// ---------------- per-layer buffer init ----------------
__global__ void init_layer_buffers()
{
    size_t i = (size_t)blockIdx.x * blockDim.x + threadIdx.x;
    size_t stride = (size_t)gridDim.x * blockDim.x;
    for (size_t k = i; k < (size_t)NN * H; k += stride) g_denom[k] = 0.f;
    float4 z = make_float4(0.f, 0.f, 0.f, 0.f);
    float4* agg4 = (float4*)g_agg;
    for (size_t k = i; k < (size_t)NN * 32; k += stride) agg4[k] = z;
}

// ---------------- fused edge pass ----------------
__global__ void __launch_bounds__(256) edge_fused(
    const int* __restrict__ s0, const int* __restrict__ d0,
    const int* __restrict__ s1, const int* __restrict__ d1,
    const int* __restrict__ s2, const int* __restrict__ d2,
    const int* __restrict__ s3, const int* __restrict__ d3,
    const float* __restrict__ KV, const float* __restrict__ Q,
    const float* __restrict__ prel, float* __restrict__ denom, float* __restrict__ agg)
{
    int gw   = (blockIdx.x * blockDim.x + threadIdx.x) >> 5;
    int lane = threadIdx.x & 31;
    if (gw >= E_TOT) return;

    const int* sp; const int* dp; int kvoff, doff, r, e = gw;
    if (gw < 150000)      { r = 0; sp = s0; dp = d0; kvoff = 0;      doff = 0; }
    else if (gw < 300000) { r = 1; sp = s1; dp = d1; kvoff = 100000; doff = 200000; e -= 150000; }
    else if (gw < 500000) { r = 2; sp = s2; dp = d2; kvoff = 300000; doff = 0;      e -= 300000; }
    else                  { r = 3; sp = s3; dp = d3; kvoff = 500000; doff = 300000; e -= 500000; }

    int s  = sp[e] + kvoff;
    int dg = dp[e] + doff;
    const float* kvrow = KV + (size_t)s * 256;

    float4 kr = *(const float4*)(kvrow + lane * 4);
    float4 q  = *(const float4*)(Q + (size_t)dg * 128 + lane * 4);
    float p = kr.x * q.x + kr.y * q.y + kr.z * q.z + kr.w * q.w;
    p += __shfl_xor_sync(0xffffffffu, p, 1);
    p += __shfl_xor_sync(0xffffffffu, p, 2);
    p += __shfl_xor_sync(0xffffffffu, p, 4);
    int h = lane >> 3;
    float a  = p * prel[r * 4 + h] * 0.17677669529663687f;
    float ea = expf(a);
    if ((lane & 7) == 0) atomicAdd(denom + (size_t)dg * 4 + h, ea);

    float4 vv = *(const float4*)(kvrow + 128 + lane * 4);
    float* o = agg + (size_t)dg * 128 + lane * 4;
    atomicAdd(o + 0, ea * vv.x);
    atomicAdd(o + 1, ea * vv.y);
    atomicAdd(o + 2, ea * vv.z);
    atomicAdd(o + 3, ea * vv.w);
}

// ---------------- host launch ----------------
extern "C" void kernel_launch(void* const* d_in, const int* in_sizes, int n_in,
                              void* d_out, int out_size)
{
    (void)in_sizes; (void)n_in; (void)out_size;

    const float* x_in[3] = {(const float*)d_in[0], (const float*)d_in[1], (const float*)d_in[2]};
    const int* esrc[4]; const int* edst[4];
    for (int r = 0; r < 4; r++) { esrc[r] = (const int*)d_in[3 + 2*r]; edst[r] = (const int*)d_in[4 + 2*r]; }
    const float* W_in   = (const float*)d_in[11];
    const float* b_in   = (const float*)d_in[12];
    const float* Wkqv   = (const float*)d_in[13];
    const float* bkqv   = (const float*)d_in[14];
    const float* Wk_rel = (const float*)d_in[15];
    const float* Wv_rel = (const float*)d_in[16];
    const float* p_rel  = (const float*)d_in[17];
    const float* Wout   = (const float*)d_in[18];
    const float* bout   = (const float*)d_in[19];
    const float* skip   = (const float*)d_in[20];
    float* out = (float*)d_out;

    float *X, *Q, *KV, *denom, *agg, *bias;
    unsigned char* wimg;
    cudaGetSymbolAddress((void**)&X,     g_X);
    cudaGetSymbolAddress((void**)&Q,     g_Q);
    cudaGetSymbolAddress((void**)&KV,    g_KV);
    cudaGetSymbolAddress((void**)&denom, g_denom);
    cudaGetSymbolAddress((void**)&agg,   g_agg);
    cudaGetSymbolAddress((void**)&wimg,  g_wimg);
    cudaGetSymbolAddress((void**)&bias,  g_bias);

    const int SMEM = 104448;
    cudaFuncSetAttribute(gemm_multi<0>, cudaFuncAttributeMaxDynamicSharedMemorySize, SMEM);
    cudaFuncSetAttribute(gemm_multi<1>, cudaFuncAttributeMaxDynamicSharedMemorySize, SMEM);
    cudaFuncSetAttribute(gemm_multi<2>, cudaFuncAttributeMaxDynamicSharedMemorySize, SMEM);

    // ---- launch 0: all plain weight preps ----
    {
        PPlainList L;
        for (int t = 0; t < 3; t++)
            L.p[t] = { W_in + (size_t)t*C*C, 128, b_in + t*128, wimg + IMG_IN(t), bias + B_IN(t) };
        for (int l = 0; l < LAYERS; l++)
            for (int t = 0; t < 3; t++) {
                L.p[3 + l*3 + t] = { Wkqv + (size_t)(l*3 + t)*C*384 + 128, 384,
                                     bkqv + (size_t)(l*3 + t)*384 + 128,
                                     wimg + IMG_Q(l,t), bias + B_Q(l,t) };
                L.p[9 + l*3 + t] = { Wout + (size_t)(l*3 + t)*C*C, 128,
                                     bout + (size_t)(l*3 + t)*128,
                                     wimg + IMG_OUT(l,t), bias + B_OUT(l,t) };
            }
        dim3 grid(64, 15);
        prep_plain_all<<<grid, 256>>>(L);
    }
    // ---- launch 1: all KV weight preps ----
    {
        static const int REL_ST_L[4] = {1, 0, 0, 0};
        PKVList L;
        for (int l = 0; l < LAYERS; l++)
            for (int r = 0; r < NR; r++) {
                int st = REL_ST_L[r];
                L.p[l*4 + r] = { Wkqv + (size_t)(l*3 + st)*C*384, bkqv + (size_t)(l*3 + st)*384,
                                 Wk_rel + (size_t)(l*NR + r)*4096, Wv_rel + (size_t)(l*NR + r)*4096,
                                 wimg + IMG_KV(l,r), bias + B_KV(l,r) };
            }
        dim3 grid(128, 8);
        prep_kv_all<<<grid, 256>>>(L);
    }

    // ---- launch 2: init layer-0 buffers ----
    init_layer_buffers<<<1024, 256>>>();

    // ---- launches 3,4,5: input linear+relu (author, keyword, paper — paper is #5 for ncu) ----
    {
        const int order[3] = {1, 2, 0};
        for (int oi = 0; oi < 3; oi++) {
            int t = order[oi];
            int M = NT_H[t];
            TileList tl; tl.n = 1;
            tl.t[0] = { wimg + IMG_IN(t), bias + B_IN(t), X + (size_t)OFFS_H[t]*C, 128, 0, 128 };
            gemm_multi<0><<<(M + 63)/64, 256, SMEM>>>(x_in[t], tl, nullptr, nullptr, nullptr, M);
        }
    }

    // relation -> (src type, kv offset); per node type, which relations it sources
    for (int l = 0; l < LAYERS; l++) {
        if (l > 0) init_layer_buffers<<<1024, 256>>>();

        // paper (type 0): Q + rel1,2,3 (2 col tiles each) = 7 tiles
        {
            TileList tl; tl.n = 7;
            tl.t[0] = { wimg + IMG_Q(l,0), bias + B_Q(l,0), Q + (size_t)OFFS_H[0]*C, 128, 0, 128 };
            int k = 1;
            for (int r = 1; r <= 3; r++)
                for (int c = 0; c < 2; c++) {
                    tl.t[k++] = { wimg + IMG_KV(l,r), bias + B_KV(l,r) + c*128,
                                  KV + (size_t)KRELOFF_H[r]*256 + c*128, 256, c*128, 256 };
                }
            gemm_multi<1><<<(NP + 63)/64, 256, SMEM>>>(X + (size_t)OFFS_H[0]*C, tl,
                                                       nullptr, nullptr, nullptr, NP);
        }
        // author (type 1): Q + rel0 (2 tiles) = 3 tiles
        {
            TileList tl; tl.n = 3;
            tl.t[0] = { wimg + IMG_Q(l,1), bias + B_Q(l,1), Q + (size_t)OFFS_H[1]*C, 128, 0, 128 };
            for (int c = 0; c < 2; c++)
                tl.t[1 + c] = { wimg + IMG_KV(l,0), bias + B_KV(l,0) + c*128,
                                KV + (size_t)KRELOFF_H[0]*256 + c*128, 256, c*128, 256 };
            gemm_multi<1><<<(NA + 63)/64, 256, SMEM>>>(X + (size_t)OFFS_H[1]*C, tl,
                                                       nullptr, nullptr, nullptr, NA);
        }
        // keyword (type 2): Q only
        {
            TileList tl; tl.n = 1;
            tl.t[0] = { wimg + IMG_Q(l,2), bias + B_Q(l,2), Q + (size_t)OFFS_H[2]*C, 128, 0, 128 };
            gemm_multi<1><<<(NKW + 63)/64, 256, SMEM>>>(X + (size_t)OFFS_H[2]*C, tl,
                                                        nullptr, nullptr, nullptr, NKW);
        }

        // fused edge pass
        edge_fused<<<(E_TOT * 32 + 255)/256, 256>>>(
            esrc[0], edst[0], esrc[1], edst[1], esrc[2], edst[2], esrc[3], edst[3],
            KV, Q, p_rel + (size_t)l*NR*H, denom, agg);

        // output projection + skip
        for (int t = 0; t < 3; t++) {
            int M = NT_H[t];
            float* Y = (l == LAYERS - 1) ? out + (size_t)OFFS_H[t]*C
                                         : X + (size_t)OFFS_H[t]*C;
            TileList tl; tl.n = 1;
            tl.t[0] = { wimg + IMG_OUT(l,t), bias + B_OUT(l,t), Y, 128, 0, 128 };
            gemm_multi<2><<<(M + 63)/64, 256, SMEM>>>(
                agg + (size_t)OFFS_H[t]*C, tl,
                X + (size_t)OFFS_H[t]*C, skip + (size_t)(l*3 + t),
                denom + (size_t)OFFS_H[t]*H, M);
        }
    }
}

// round 6
// speedup vs baseline: 2.9600x; 1.0489x over previous
#include <cuda_runtime.h>
#include <cuda_bf16.h>
#include <math.h>
#include <stdint.h>

// ---------------- problem constants ----------------
#define NP 200000
#define NA 100000
#define NKW 50000
#define NN 350000
#define C 128
#define H 4
#define D 32
#define LAYERS 2
#define NR 4
#define E_TOT 600000
#define SRC_TOT 700000   // rel0: A(100k) srcs, rel1-3: P(200k) each

static const int OFFS_H[3]     = {0, NP, NP + NA};
static const int KRELOFF_H[4]  = {0, NA, NA + NP, NA + 2*NP};
static const int NT_H[3]       = {NP, NA, NKW};

// ---------------- scratch ----------------
__device__ float g_X    [(size_t)NN * C];
__device__ float g_Q    [(size_t)NN * C];
__device__ float g_KV   [(size_t)SRC_TOT * 256];   // [Krel(128) | Vrel(128)] per (rel,node)
__device__ float g_denom[(size_t)NN * H];
__device__ float g_agg  [(size_t)NN * C];
__device__ unsigned char g_wimg[2031616];
__device__ float g_bias[3968];
// CSR (built once)
__device__ int g_counts[NN];
__device__ int g_starts[NN];
__device__ int g_cursor[NN];
__device__ int g_bsums[512];
__device__ int g_boffs[512];
__device__ unsigned int g_eidx[E_TOT];

#define IMG_IN(t)     ((size_t)(t) * 65536)
#define IMG_Q(l,t)    ((size_t)(3 + (l)*3 + (t)) * 65536)
#define IMG_OUT(l,t)  ((size_t)(9 + (l)*3 + (t)) * 65536)
#define IMG_KV(l,r)   ((size_t)15 * 65536 + (size_t)((l)*4 + (r)) * 131072)
#define B_IN(t)     ((t) * 128)
#define B_Q(l,t)    (384 + ((l)*3 + (t)) * 128)
#define B_OUT(l,t)  (1152 + ((l)*3 + (t)) * 128)
#define B_KV(l,r)   (1920 + ((l)*4 + (r)) * 256)

// ---------------- helpers ----------------
__device__ __forceinline__ uint32_t smem_to_u32(const void* p) {
    uint32_t a;
    asm("{ .reg .u64 t; cvta.to.shared.u64 t, %1; cvt.u32.u64 %0, t; }" : "=r"(a) : "l"(p));
    return a;
}
__device__ __forceinline__ float gelu_f(float x) {
    return 0.5f * x * (1.0f + erff(x * 0.70710678118654752440f));
}
__device__ __forceinline__ void ldm_x4(uint32_t* r, uint32_t a) {
    asm volatile("ldmatrix.sync.aligned.m8n8.x4.shared.b16 {%0,%1,%2,%3}, [%4];"
                 : "=r"(r[0]), "=r"(r[1]), "=r"(r[2]), "=r"(r[3]) : "r"(a));
}
__device__ __forceinline__ void ldm_x4_t(uint32_t* r, uint32_t a) {
    asm volatile("ldmatrix.sync.aligned.m8n8.x4.trans.shared.b16 {%0,%1,%2,%3}, [%4];"
                 : "=r"(r[0]), "=r"(r[1]), "=r"(r[2]), "=r"(r[3]) : "r"(a));
}
__device__ __forceinline__ void mma_bf16(float* d, const uint32_t* a, const uint32_t* b) {
    asm volatile(
        "mma.sync.aligned.m16n8k16.row.col.f32.bf16.bf16.f32 "
        "{%0,%1,%2,%3}, {%4,%5,%6,%7}, {%8,%9}, {%0,%1,%2,%3};"
        : "+f"(d[0]), "+f"(d[1]), "+f"(d[2]), "+f"(d[3])
        : "r"(a[0]), "r"(a[1]), "r"(a[2]), "r"(a[3]), "r"(b[0]), "r"(b[1]));
}

// ---------------- batched weight prep ----------------
struct PPlain { const float* W; long ldW; const float* bias; unsigned char* img; float* bOut; };
struct PPlainList { PPlain p[15]; };

__global__ void prep_plain_all(PPlainList L)
{
    const PPlain pp = L.p[blockIdx.y];
    int idx = blockIdx.x * blockDim.x + threadIdx.x;   // 0..16383
    int n = idx & 127, k = idx >> 7;
    float v = pp.W[(size_t)k * pp.ldW + n];
    uint32_t u = __float_as_uint(v);
    uint32_t hb = u & 0xFFFF0000u;
    float lo = v - __uint_as_float(hb);
    size_t off = ((size_t)k * 128 + n) * 2;
    *(unsigned short*)(pp.img + off) = (unsigned short)(hb >> 16);
    *(__nv_bfloat16*)(pp.img + 32768 + off) = __float2bfloat16(lo);
    if (k == 0) pp.bOut[n] = pp.bias[n];
}

struct PKV { const float* Wkqv; const float* bkqv; const float* Wk; const float* Wv;
             unsigned char* img; float* bOut; };
struct PKVList { PKV p[8]; };

__global__ void prep_kv_all(PKVList L)
{
    const PKV pp = L.p[blockIdx.y];
    int idx = blockIdx.x * blockDim.x + threadIdx.x;   // 0..32767
    int n = idx & 255, k = idx >> 8;
    int isV = n >> 7, nn = n & 127, h = nn >> 5, f = nn & 31;
    const float* Wr = isV ? pp.Wv : pp.Wk;
    int kqvOff = isV ? 256 : 0;
    float v = 0.f;
#pragma unroll
    for (int d = 0; d < 32; d++)
        v += pp.Wkqv[(size_t)k * 384 + kqvOff + h * 32 + d] * Wr[h * 1024 + d * 32 + f];
    uint32_t u = __float_as_uint(v);
    uint32_t hb = u & 0xFFFF0000u;
    float lo = v - __uint_as_float(hb);
    size_t off = ((size_t)k * 256 + n) * 2;
    *(unsigned short*)(pp.img + off) = (unsigned short)(hb >> 16);
    *(__nv_bfloat16*)(pp.img + 65536 + off) = __float2bfloat16(lo);
    if (k == 0) {
        float b = 0.f;
#pragma unroll
        for (int d = 0; d < 32; d++)
            b += pp.bkqv[kqvOff + h * 32 + d] * Wr[h * 1024 + d * 32 + f];
        pp.bOut[n] = b;
    }
}

// ---------------- multi-tile HMMA GEMM ----------------
struct Tile {
    const unsigned char* img;
    const float* bias;
    float* out;
    int imgNC;
    int colBase;
    int stride;
};
struct TileList { Tile t[7]; int n; };

template <int MODE>
__global__ void __launch_bounds__(256, 2) gemm_multi(
    const float* __restrict__ Ain, TileList tl,
    const float* __restrict__ Xold, const float* __restrict__ skipPtr,
    const float* __restrict__ denomPtr, int M)
{
    extern __shared__ char sm[];
    const int S = 272;
    const int A_HI = 0, A_LO = 17408, B_HI = 34816, B_LO = 69632;

    const int tid = threadIdx.x, lane = tid & 31, w = tid >> 5;
    const int rowBase = blockIdx.x * 64;
    const uint32_t smu = smem_to_u32(sm);

#pragma unroll
    for (int j = 0; j < 8; j++) {
        int f = j * 256 + tid;
        int row = f >> 5, col = (f & 31) * 4;
        float4 v = make_float4(0.f, 0.f, 0.f, 0.f);
        int gr = rowBase + row;
        if (gr < M) v = *(const float4*)(Ain + (size_t)gr * 128 + col);
        if (MODE == 2) {
            float inv = 1.f / fmaxf(denomPtr[(size_t)gr * 4 + (col >> 5)], 1e-16f);
            v.x = gelu_f(v.x * inv); v.y = gelu_f(v.y * inv);
            v.z = gelu_f(v.z * inv); v.w = gelu_f(v.w * inv);
        }
        uint32_t ux = __float_as_uint(v.x), uy = __float_as_uint(v.y);
        uint32_t uz = __float_as_uint(v.z), uw = __float_as_uint(v.w);
        uint32_t hi01 = __byte_perm(ux, uy, 0x7632);
        uint32_t hi23 = __byte_perm(uz, uw, 0x7632);
        float lx = v.x - __uint_as_float(ux & 0xFFFF0000u);
        float ly = v.y - __uint_as_float(uy & 0xFFFF0000u);
        float lz = v.z - __uint_as_float(uz & 0xFFFF0000u);
        float lw = v.w - __uint_as_float(uw & 0xFFFF0000u);
        uint32_t lo01, lo23;
        asm("cvt.rn.satfinite.bf16x2.f32 %0, %1, %2;" : "=r"(lo01) : "f"(ly), "f"(lx));
        asm("cvt.rn.satfinite.bf16x2.f32 %0, %1, %2;" : "=r"(lo23) : "f"(lw), "f"(lz));
        *(uint2*)(sm + A_HI + row * S + col * 2) = make_uint2(hi01, hi23);
        *(uint2*)(sm + A_LO + row * S + col * 2) = make_uint2(lo01, lo23);
    }

    float sg = 0.f, og = 0.f;
    if (MODE == 2) { sg = 1.f / (1.f + expf(-*skipPtr)); og = 1.f - sg; }

    const int wm = w & 3, wn = w >> 2;
    const int lr = lane & 15, lc = lane >> 4;
    const uint32_t aHi = smu + A_HI + (wm * 16 + lr) * S + lc * 16;
    const uint32_t aLo = aHi + 17408;
    const uint32_t bHiBase = smu + B_HI + lr * S + (wn * 64 + lc * 8) * 2;
    const int gid = lane >> 2, tc = (lane & 3) * 2;

    for (int ti = 0; ti < tl.n; ti++) {
        const Tile tile = tl.t[ti];

#pragma unroll
        for (int j = 0; j < 16; j++) {
            int idx = j * 256 + tid;
            int im = idx >> 11;
            int id = idx & 2047;
            int row = id >> 4, q = id & 15;
            const unsigned char* base = tile.img + (size_t)im * tile.imgNC * 256;
            uint4 v = *(const uint4*)(base + ((size_t)row * tile.imgNC + tile.colBase) * 2 + q * 16);
            *(uint4*)(sm + (im ? B_LO : B_HI) + row * S + q * 16) = v;
        }
        __syncthreads();

        float acc[8][4];
#pragma unroll
        for (int nj = 0; nj < 8; nj++)
#pragma unroll
            for (int q = 0; q < 4; q++) acc[nj][q] = 0.f;

#pragma unroll
        for (int ks = 0; ks < 8; ks++) {
            uint32_t ah[4], al[4], bh[4][4], bl[4][4];
            ldm_x4(ah, aHi + ks * 32);
            ldm_x4(al, aLo + ks * 32);
#pragma unroll
            for (int nb = 0; nb < 4; nb++) {
                ldm_x4_t(bh[nb], bHiBase + ks * 16 * S + nb * 32);
                ldm_x4_t(bl[nb], bHiBase + 34816 + ks * 16 * S + nb * 32);
            }
#pragma unroll
            for (int nj = 0; nj < 8; nj++) {
                const uint32_t* bfh = &bh[nj >> 1][(nj & 1) * 2];
                const uint32_t* bfl = &bl[nj >> 1][(nj & 1) * 2];
                mma_bf16(acc[nj], ah, bfh);
                mma_bf16(acc[nj], ah, bfl);
                mma_bf16(acc[nj], al, bfh);
            }
        }

#pragma unroll
        for (int nj = 0; nj < 8; nj++) {
            int col = wn * 64 + nj * 8 + tc;
            float b0 = __ldg(tile.bias + col), b1 = __ldg(tile.bias + col + 1);
#pragma unroll
            for (int half = 0; half < 2; half++) {
                int row = rowBase + wm * 16 + gid + half * 8;
                if (row >= M) continue;
                float o0 = acc[nj][half * 2 + 0] + b0;
                float o1 = acc[nj][half * 2 + 1] + b1;
                if (MODE == 0) {
                    o0 = fmaxf(o0, 0.f); o1 = fmaxf(o1, 0.f);
                } else if (MODE == 2) {
                    float2 xo = *(const float2*)(Xold + (size_t)row * 128 + col);
                    o0 = sg * o0 + og * xo.x;
                    o1 = sg * o1 + og * xo.y;
                }
                *(float2*)(tile.out + (size_t)row * tile.stride + col) = make_float2(o0, o1);
            }
        }
        __syncthreads();
    }
}

// ---------------- CSR build (once per run; edges are layer-invariant) ----------------
__global__ void zero_counts()
{
    int i = blockIdx.x * blockDim.x + threadIdx.x;
    if (i < NN) g_counts[i] = 0;
}

__device__ __forceinline__ void edge_map(int gw,
    const int* s0, const int* d0, const int* s1, const int* d1,
    const int* s2, const int* d2, const int* s3, const int* d3,
    int& kvi, int& dg)
{
    const int* sp; const int* dp; int kvoff, doff, e = gw;
    if (gw < 150000)      { sp = s0; dp = d0; kvoff = 0;      doff = 0; }
    else if (gw < 300000) { sp = s1; dp = d1; kvoff = 100000; doff = 200000; e -= 150000; }
    else if (gw < 500000) { sp = s2; dp = d2; kvoff = 300000; doff = 0;      e -= 300000; }
    else                  { sp = s3; dp = d3; kvoff = 500000; doff = 300000; e -= 500000; }
    kvi = sp[e] + kvoff;
    dg  = dp[e] + doff;
}

__global__ void hist_edges(const int* s0, const int* d0, const int* s1, const int* d1,
                           const int* s2, const int* d2, const int* s3, const int* d3)
{
    int gw = blockIdx.x * blockDim.x + threadIdx.x;
    if (gw >= E_TOT) return;
    int kvi, dg;
    edge_map(gw, s0, d0, s1, d1, s2, d2, s3, d3, kvi, dg);
    atomicAdd(&g_counts[dg], 1);
}

__global__ void scan_blocks()   // grid 342, block 1024: exclusive scan within block
{
    __shared__ int smv[1024];
    int i = blockIdx.x * 1024 + threadIdx.x;
    int v = (i < NN) ? g_counts[i] : 0;
    smv[threadIdx.x] = v;
    __syncthreads();
#pragma unroll
    for (int off = 1; off < 1024; off <<= 1) {
        int t = (threadIdx.x >= off) ? smv[threadIdx.x - off] : 0;
        __syncthreads();
        smv[threadIdx.x] += t;
        __syncthreads();
    }
    if (i < NN) g_starts[i] = smv[threadIdx.x] - v;
    if (threadIdx.x == 1023) g_bsums[blockIdx.x] = smv[1023];
}

__global__ void scan_sums(int nb)   // single block 1024
{
    __shared__ int smv[1024];
    int v = (threadIdx.x < nb) ? g_bsums[threadIdx.x] : 0;
    smv[threadIdx.x] = v;
    __syncthreads();
#pragma unroll
    for (int off = 1; off < 1024; off <<= 1) {
        int t = (threadIdx.x >= off) ? smv[threadIdx.x - off] : 0;
        __syncthreads();
        smv[threadIdx.x] += t;
        __syncthreads();
    }
    if (threadIdx.x < nb) g_boffs[threadIdx.x] = smv[threadIdx.x] - v;
}

__global__ void scan_finish()   // grid 342, block 1024
{
    int i = blockIdx.x * 1024 + threadIdx.x;
    if (i < NN) {
        int s = g_starts[i] + g_boffs[blockIdx.x];
        g_starts[i] = s;
        g_cursor[i] = s;
    }
}

__global__ void scatter_edges(const int* s0, const int* d0, const int* s1, const int* d1,
                              const int* s2, const int* d2, const int* s3, const int* d3)
{
    int gw = blockIdx.x * blockDim.x + threadIdx.x;
    if (gw >= E_TOT) return;
    int kvi, dg;
    edge_map(gw, s0, d0, s1, d1, s2, d2, s3, d3, kvi, dg);
    int pos = atomicAdd(&g_cursor[dg], 1);
    g_eidx[pos] = (unsigned int)kvi;
}

// ---------------- gather: warp per dst node, no atomics ----------------
__global__ void __launch_bounds__(256) gather_nodes(
    const float* __restrict__ KV, const float* __restrict__ Q,
    const float* __restrict__ prel, float* __restrict__ denom, float* __restrict__ agg)
{
    int n    = (blockIdx.x * blockDim.x + threadIdx.x) >> 5;
    int lane = threadIdx.x & 31;
    if (n >= NN) return;

    float4 q = *(const float4*)(Q + (size_t)n * 128 + lane * 4);
    int start = g_starts[n];
    int cnt   = g_counts[n];
    int h = lane >> 3;

    float a0 = 0.f, a1 = 0.f, a2 = 0.f, a3 = 0.f, dsum = 0.f;
    for (int j = 0; j < cnt; j++) {
        int kvi = (int)g_eidx[start + j];
        int r = (kvi < 100000) ? 0 : (kvi < 300000) ? 1 : (kvi < 500000) ? 2 : 3;
        const float* kvrow = KV + (size_t)kvi * 256;
        float4 kr = *(const float4*)(kvrow + lane * 4);
        float p = kr.x * q.x + kr.y * q.y + kr.z * q.z + kr.w * q.w;
        p += __shfl_xor_sync(0xffffffffu, p, 1);
        p += __shfl_xor_sync(0xffffffffu, p, 2);
        p += __shfl_xor_sync(0xffffffffu, p, 4);
        float a  = p * __ldg(prel + r * 4 + h) * 0.17677669529663687f;
        float ea = expf(a);
        dsum += ea;
        float4 vv = *(const float4*)(kvrow + 128 + lane * 4);
        a0 += ea * vv.x; a1 += ea * vv.y; a2 += ea * vv.z; a3 += ea * vv.w;
    }
    *(float4*)(agg + (size_t)n * 128 + lane * 4) = make_float4(a0, a1, a2, a3);
    if ((lane & 7) == 0) denom[(size_t)n * 4 + h] = dsum;
}

// ---------------- host launch ----------------
extern "C" void kernel_launch(void* const* d_in, const int* in_sizes, int n_in,
                              void* d_out, int out_size)
{
    (void)in_sizes; (void)n_in; (void)out_size;

    const float* x_in[3] = {(const float*)d_in[0], (const float*)d_in[1], (const float*)d_in[2]};
    const int* esrc[4]; const int* edst[4];
    for (int r = 0; r < 4; r++) { esrc[r] = (const int*)d_in[3 + 2*r]; edst[r] = (const int*)d_in[4 + 2*r]; }
    const float* W_in   = (const float*)d_in[11];
    const float* b_in   = (const float*)d_in[12];
    const float* Wkqv   = (const float*)d_in[13];
    const float* bkqv   = (const float*)d_in[14];
    const float* Wk_rel = (const float*)d_in[15];
    const float* Wv_rel = (const float*)d_in[16];
    const float* p_rel  = (const float*)d_in[17];
    const float* Wout   = (const float*)d_in[18];
    const float* bout   = (const float*)d_in[19];
    const float* skip   = (const float*)d_in[20];
    float* out = (float*)d_out;

    float *X, *Q, *KV, *denom, *agg, *bias;
    unsigned char* wimg;
    cudaGetSymbolAddress((void**)&X,     g_X);
    cudaGetSymbolAddress((void**)&Q,     g_Q);
    cudaGetSymbolAddress((void**)&KV,    g_KV);
    cudaGetSymbolAddress((void**)&denom, g_denom);
    cudaGetSymbolAddress((void**)&agg,   g_agg);
    cudaGetSymbolAddress((void**)&wimg,  g_wimg);
    cudaGetSymbolAddress((void**)&bias,  g_bias);

    const int SMEM = 104448;
    cudaFuncSetAttribute(gemm_multi<0>, cudaFuncAttributeMaxDynamicSharedMemorySize, SMEM);
    cudaFuncSetAttribute(gemm_multi<1>, cudaFuncAttributeMaxDynamicSharedMemorySize, SMEM);
    cudaFuncSetAttribute(gemm_multi<2>, cudaFuncAttributeMaxDynamicSharedMemorySize, SMEM);

    const int NB = (NN + 1023) / 1024;   // 342

    // ---- launch 0: plain weight preps ----
    {
        PPlainList L;
        for (int t = 0; t < 3; t++)
            L.p[t] = { W_in + (size_t)t*C*C, 128, b_in + t*128, wimg + IMG_IN(t), bias + B_IN(t) };
        for (int l = 0; l < LAYERS; l++)
            for (int t = 0; t < 3; t++) {
                L.p[3 + l*3 + t] = { Wkqv + (size_t)(l*3 + t)*C*384 + 128, 384,
                                     bkqv + (size_t)(l*3 + t)*384 + 128,
                                     wimg + IMG_Q(l,t), bias + B_Q(l,t) };
                L.p[9 + l*3 + t] = { Wout + (size_t)(l*3 + t)*C*C, 128,
                                     bout + (size_t)(l*3 + t)*128,
                                     wimg + IMG_OUT(l,t), bias + B_OUT(l,t) };
            }
        dim3 grid(64, 15);
        prep_plain_all<<<grid, 256>>>(L);
    }
    // ---- launch 1: KV weight preps ----
    {
        static const int REL_ST_L[4] = {1, 0, 0, 0};
        PKVList L;
        for (int l = 0; l < LAYERS; l++)
            for (int r = 0; r < NR; r++) {
                int st = REL_ST_L[r];
                L.p[l*4 + r] = { Wkqv + (size_t)(l*3 + st)*C*384, bkqv + (size_t)(l*3 + st)*384,
                                 Wk_rel + (size_t)(l*NR + r)*4096, Wv_rel + (size_t)(l*NR + r)*4096,
                                 wimg + IMG_KV(l,r), bias + B_KV(l,r) };
            }
        dim3 grid(128, 8);
        prep_kv_all<<<grid, 256>>>(L);
    }

    // ---- launches 2,3,4: input linear+relu (author, keyword, paper) ----
    {
        const int order[3] = {1, 2, 0};
        for (int oi = 0; oi < 3; oi++) {
            int t = order[oi];
            int M = NT_H[t];
            TileList tl; tl.n = 1;
            tl.t[0] = { wimg + IMG_IN(t), bias + B_IN(t), X + (size_t)OFFS_H[t]*C, 128, 0, 128 };
            gemm_multi<0><<<(M + 63)/64, 256, SMEM>>>(x_in[t], tl, nullptr, nullptr, nullptr, M);
        }
    }

    // ---- launch 5: layer-0 paper 7-tile GEMM (ncu profile target) ----
    for (int l = 0; l < LAYERS; l++) {
        // paper (type 0): Q + rel1,2,3 (2 col tiles each) = 7 tiles
        {
            TileList tl; tl.n = 7;
            tl.t[0] = { wimg + IMG_Q(l,0), bias + B_Q(l,0), Q + (size_t)OFFS_H[0]*C, 128, 0, 128 };
            int k = 1;
            for (int r = 1; r <= 3; r++)
                for (int c = 0; c < 2; c++)
                    tl.t[k++] = { wimg + IMG_KV(l,r), bias + B_KV(l,r) + c*128,
                                  KV + (size_t)KRELOFF_H[r]*256 + c*128, 256, c*128, 256 };
            gemm_multi<1><<<(NP + 63)/64, 256, SMEM>>>(X + (size_t)OFFS_H[0]*C, tl,
                                                       nullptr, nullptr, nullptr, NP);
        }
        // author (type 1): Q + rel0 = 3 tiles
        {
            TileList tl; tl.n = 3;
            tl.t[0] = { wimg + IMG_Q(l,1), bias + B_Q(l,1), Q + (size_t)OFFS_H[1]*C, 128, 0, 128 };
            for (int c = 0; c < 2; c++)
                tl.t[1 + c] = { wimg + IMG_KV(l,0), bias + B_KV(l,0) + c*128,
                                KV + (size_t)KRELOFF_H[0]*256 + c*128, 256, c*128, 256 };
            gemm_multi<1><<<(NA + 63)/64, 256, SMEM>>>(X + (size_t)OFFS_H[1]*C, tl,
                                                       nullptr, nullptr, nullptr, NA);
        }
        // keyword (type 2): Q only
        {
            TileList tl; tl.n = 1;
            tl.t[0] = { wimg + IMG_Q(l,2), bias + B_Q(l,2), Q + (size_t)OFFS_H[2]*C, 128, 0, 128 };
            gemm_multi<1><<<(NKW + 63)/64, 256, SMEM>>>(X + (size_t)OFFS_H[2]*C, tl,
                                                        nullptr, nullptr, nullptr, NKW);
        }

        if (l == 0) {
            // CSR build (once; independent of Q/KV but placed here to keep
            // the ncu -s 5 window on the big GEMM above)
            zero_counts<<<(NN + 255)/256, 256>>>();
            hist_edges<<<(E_TOT + 255)/256, 256>>>(esrc[0], edst[0], esrc[1], edst[1],
                                                   esrc[2], edst[2], esrc[3], edst[3]);
            scan_blocks<<<NB, 1024>>>();
            scan_sums<<<1, 1024>>>(NB);
            scan_finish<<<NB, 1024>>>();
            scatter_edges<<<(E_TOT + 255)/256, 256>>>(esrc[0], edst[0], esrc[1], edst[1],
                                                      esrc[2], edst[2], esrc[3], edst[3]);
        }

        // gather (atomic-free)
        gather_nodes<<<(NN * 32 + 255)/256, 256>>>(KV, Q, p_rel + (size_t)l*NR*H, denom, agg);

        // output projection + skip
        for (int t = 0; t < 3; t++) {
            int M = NT_H[t];
            float* Y = (l == LAYERS - 1) ? out + (size_t)OFFS_H[t]*C
                                         : X + (size_t)OFFS_H[t]*C;
            TileList tl; tl.n = 1;
            tl.t[0] = { wimg + IMG_OUT(l,t), bias + B_OUT(l,t), Y, 128, 0, 128 };
            gemm_multi<2><<<(M + 63)/64, 256, SMEM>>>(
                agg + (size_t)OFFS_H[t]*C, tl,
                X + (size_t)OFFS_H[t]*C, skip + (size_t)(l*3 + t),
                denom + (size_t)OFFS_H[t]*H, M);
        }
    }
}

// round 7
// speedup vs baseline: 2.9614x; 1.0004x over previous
#include <cuda_runtime.h>
#include <cuda_bf16.h>
#include <math.h>
#include <stdint.h>

// ---------------- problem constants ----------------
#define NP 200000
#define NA 100000
#define NKW 50000
#define NN 350000
#define C 128
#define H 4
#define D 32
#define LAYERS 2
#define NR 4
#define E_TOT 600000
#define SRC_TOT 700000   // rel0: A(100k) srcs, rel1-3: P(200k) each

static const int OFFS_H[3]     = {0, NP, NP + NA};
static const int KRELOFF_H[4]  = {0, NA, NA + NP, NA + 2*NP};
static const int NT_H[3]       = {NP, NA, NKW};

// ---------------- scratch ----------------
__device__ float g_X    [(size_t)NN * C];
__device__ float g_Q    [(size_t)NN * C];
__device__ float g_KV   [(size_t)SRC_TOT * 256];   // [Krel(128) | Vrel(128)] per (rel,node)
__device__ float g_denom[(size_t)NN * H];
__device__ float g_agg  [(size_t)NN * C];
__device__ unsigned char g_wimg[2031616];
__device__ float g_bias[3968];
// CSR (built once)
__device__ int g_counts[NN];
__device__ int g_starts[NN];
__device__ int g_cursor[NN];
__device__ int g_bsums[512];
__device__ int g_boffs[512];
__device__ unsigned int g_eidx[E_TOT];

#define IMG_IN(t)     ((size_t)(t) * 65536)
#define IMG_Q(l,t)    ((size_t)(3 + (l)*3 + (t)) * 65536)
#define IMG_OUT(l,t)  ((size_t)(9 + (l)*3 + (t)) * 65536)
#define IMG_KV(l,r)   ((size_t)15 * 65536 + (size_t)((l)*4 + (r)) * 131072)
#define B_IN(t)     ((t) * 128)
#define B_Q(l,t)    (384 + ((l)*3 + (t)) * 128)
#define B_OUT(l,t)  (1152 + ((l)*3 + (t)) * 128)
#define B_KV(l,r)   (1920 + ((l)*4 + (r)) * 256)

// ---------------- helpers ----------------
__device__ __forceinline__ uint32_t smem_to_u32(const void* p) {
    uint32_t a;
    asm("{ .reg .u64 t; cvta.to.shared.u64 t, %1; cvt.u32.u64 %0, t; }" : "=r"(a) : "l"(p));
    return a;
}
__device__ __forceinline__ float gelu_f(float x) {
    return 0.5f * x * (1.0f + erff(x * 0.70710678118654752440f));
}
__device__ __forceinline__ void ldm_x4(uint32_t* r, uint32_t a) {
    asm volatile("ldmatrix.sync.aligned.m8n8.x4.shared.b16 {%0,%1,%2,%3}, [%4];"
                 : "=r"(r[0]), "=r"(r[1]), "=r"(r[2]), "=r"(r[3]) : "r"(a));
}
__device__ __forceinline__ void ldm_x4_t(uint32_t* r, uint32_t a) {
    asm volatile("ldmatrix.sync.aligned.m8n8.x4.trans.shared.b16 {%0,%1,%2,%3}, [%4];"
                 : "=r"(r[0]), "=r"(r[1]), "=r"(r[2]), "=r"(r[3]) : "r"(a));
}
__device__ __forceinline__ void mma_bf16(float* d, const uint32_t* a, const uint32_t* b) {
    asm volatile(
        "mma.sync.aligned.m16n8k16.row.col.f32.bf16.bf16.f32 "
        "{%0,%1,%2,%3}, {%4,%5,%6,%7}, {%8,%9}, {%0,%1,%2,%3};"
        : "+f"(d[0]), "+f"(d[1]), "+f"(d[2]), "+f"(d[3])
        : "r"(a[0]), "r"(a[1]), "r"(a[2]), "r"(a[3]), "r"(b[0]), "r"(b[1]));
}

// ---------------- batched weight prep ----------------
struct PPlain { const float* W; long ldW; const float* bias; unsigned char* img; float* bOut; };
struct PPlainList { PPlain p[15]; };

__global__ void prep_plain_all(PPlainList L)
{
    const PPlain pp = L.p[blockIdx.y];
    int idx = blockIdx.x * blockDim.x + threadIdx.x;   // 0..16383
    int n = idx & 127, k = idx >> 7;
    float v = pp.W[(size_t)k * pp.ldW + n];
    uint32_t u = __float_as_uint(v);
    uint32_t hb = u & 0xFFFF0000u;
    float lo = v - __uint_as_float(hb);
    size_t off = ((size_t)k * 128 + n) * 2;
    *(unsigned short*)(pp.img + off) = (unsigned short)(hb >> 16);
    *(__nv_bfloat16*)(pp.img + 32768 + off) = __float2bfloat16(lo);
    if (k == 0) pp.bOut[n] = pp.bias[n];
}

struct PKV { const float* Wkqv; const float* bkqv; const float* Wk; const float* Wv;
             unsigned char* img; float* bOut; };
struct PKVList { PKV p[8]; };

__global__ void prep_kv_all(PKVList L)
{
    const PKV pp = L.p[blockIdx.y];
    int idx = blockIdx.x * blockDim.x + threadIdx.x;   // 0..32767
    int n = idx & 255, k = idx >> 8;
    int isV = n >> 7, nn = n & 127, h = nn >> 5, f = nn & 31;
    const float* Wr = isV ? pp.Wv : pp.Wk;
    int kqvOff = isV ? 256 : 0;
    float v = 0.f;
#pragma unroll
    for (int d = 0; d < 32; d++)
        v += pp.Wkqv[(size_t)k * 384 + kqvOff + h * 32 + d] * Wr[h * 1024 + d * 32 + f];
    uint32_t u = __float_as_uint(v);
    uint32_t hb = u & 0xFFFF0000u;
    float lo = v - __uint_as_float(hb);
    size_t off = ((size_t)k * 256 + n) * 2;
    *(unsigned short*)(pp.img + off) = (unsigned short)(hb >> 16);
    *(__nv_bfloat16*)(pp.img + 65536 + off) = __float2bfloat16(lo);
    if (k == 0) {
        float b = 0.f;
#pragma unroll
        for (int d = 0; d < 32; d++)
            b += pp.bkqv[kqvOff + h * 32 + d] * Wr[h * 1024 + d * 32 + f];
        pp.bOut[n] = b;
    }
}

// ---------------- multi-tile HMMA GEMM ----------------
struct Tile {
    const unsigned char* img;
    const float* bias;
    float* out;
    int imgNC;
    int colBase;
    int stride;
};
struct TileList { Tile t[7]; int n; };

template <int MODE>
__global__ void __launch_bounds__(256, 2) gemm_multi(
    const float* __restrict__ Ain, TileList tl,
    const float* __restrict__ Xold, const float* __restrict__ skipPtr,
    const float* __restrict__ denomPtr, int M)
{
    extern __shared__ char sm[];
    const int S = 272;
    const int A_HI = 0, A_LO = 17408, B_HI = 34816, B_LO = 69632;

    const int tid = threadIdx.x, lane = tid & 31, w = tid >> 5;
    const int rowBase = blockIdx.x * 64;
    const uint32_t smu = smem_to_u32(sm);

#pragma unroll
    for (int j = 0; j < 8; j++) {
        int f = j * 256 + tid;
        int row = f >> 5, col = (f & 31) * 4;
        float4 v = make_float4(0.f, 0.f, 0.f, 0.f);
        int gr = rowBase + row;
        if (gr < M) v = *(const float4*)(Ain + (size_t)gr * 128 + col);
        if (MODE == 2) {
            float inv = 1.f / fmaxf(denomPtr[(size_t)gr * 4 + (col >> 5)], 1e-16f);
            v.x = gelu_f(v.x * inv); v.y = gelu_f(v.y * inv);
            v.z = gelu_f(v.z * inv); v.w = gelu_f(v.w * inv);
        }
        uint32_t ux = __float_as_uint(v.x), uy = __float_as_uint(v.y);
        uint32_t uz = __float_as_uint(v.z), uw = __float_as_uint(v.w);
        uint32_t hi01 = __byte_perm(ux, uy, 0x7632);
        uint32_t hi23 = __byte_perm(uz, uw, 0x7632);
        float lx = v.x - __uint_as_float(ux & 0xFFFF0000u);
        float ly = v.y - __uint_as_float(uy & 0xFFFF0000u);
        float lz = v.z - __uint_as_float(uz & 0xFFFF0000u);
        float lw = v.w - __uint_as_float(uw & 0xFFFF0000u);
        uint32_t lo01, lo23;
        asm("cvt.rn.satfinite.bf16x2.f32 %0, %1, %2;" : "=r"(lo01) : "f"(ly), "f"(lx));
        asm("cvt.rn.satfinite.bf16x2.f32 %0, %1, %2;" : "=r"(lo23) : "f"(lw), "f"(lz));
        *(uint2*)(sm + A_HI + row * S + col * 2) = make_uint2(hi01, hi23);
        *(uint2*)(sm + A_LO + row * S + col * 2) = make_uint2(lo01, lo23);
    }

    float sg = 0.f, og = 0.f;
    if (MODE == 2) { sg = 1.f / (1.f + expf(-*skipPtr)); og = 1.f - sg; }

    const int wm = w & 3, wn = w >> 2;
    const int lr = lane & 15, lc = lane >> 4;
    const uint32_t aHi = smu + A_HI + (wm * 16 + lr) * S + lc * 16;
    const uint32_t aLo = aHi + 17408;
    const uint32_t bHiBase = smu + B_HI + lr * S + (wn * 64 + lc * 8) * 2;
    const int gid = lane >> 2, tc = (lane & 3) * 2;

    for (int ti = 0; ti < tl.n; ti++) {
        const Tile tile = tl.t[ti];

#pragma unroll
        for (int j = 0; j < 16; j++) {
            int idx = j * 256 + tid;
            int im = idx >> 11;
            int id = idx & 2047;
            int row = id >> 4, q = id & 15;
            const unsigned char* base = tile.img + (size_t)im * tile.imgNC * 256;
            uint4 v = *(const uint4*)(base + ((size_t)row * tile.imgNC + tile.colBase) * 2 + q * 16);
            *(uint4*)(sm + (im ? B_LO : B_HI) + row * S + q * 16) = v;
        }
        __syncthreads();

        float acc[8][4];
#pragma unroll
        for (int nj = 0; nj < 8; nj++)
#pragma unroll
            for (int q = 0; q < 4; q++) acc[nj][q] = 0.f;

#pragma unroll
        for (int ks = 0; ks < 8; ks++) {
            uint32_t ah[4], al[4], bh[4][4], bl[4][4];
            ldm_x4(ah, aHi + ks * 32);
            ldm_x4(al, aLo + ks * 32);
#pragma unroll
            for (int nb = 0; nb < 4; nb++) {
                ldm_x4_t(bh[nb], bHiBase + ks * 16 * S + nb * 32);
                ldm_x4_t(bl[nb], bHiBase + 34816 + ks * 16 * S + nb * 32);
            }
#pragma unroll
            for (int nj = 0; nj < 8; nj++) {
                const uint32_t* bfh = &bh[nj >> 1][(nj & 1) * 2];
                const uint32_t* bfl = &bl[nj >> 1][(nj & 1) * 2];
                mma_bf16(acc[nj], ah, bfh);
                mma_bf16(acc[nj], ah, bfl);
                mma_bf16(acc[nj], al, bfh);
            }
        }

#pragma unroll
        for (int nj = 0; nj < 8; nj++) {
            int col = wn * 64 + nj * 8 + tc;
            float b0 = __ldg(tile.bias + col), b1 = __ldg(tile.bias + col + 1);
#pragma unroll
            for (int half = 0; half < 2; half++) {
                int row = rowBase + wm * 16 + gid + half * 8;
                if (row >= M) continue;
                float o0 = acc[nj][half * 2 + 0] + b0;
                float o1 = acc[nj][half * 2 + 1] + b1;
                if (MODE == 0) {
                    o0 = fmaxf(o0, 0.f); o1 = fmaxf(o1, 0.f);
                } else if (MODE == 2) {
                    float2 xo = *(const float2*)(Xold + (size_t)row * 128 + col);
                    o0 = sg * o0 + og * xo.x;
                    o1 = sg * o1 + og * xo.y;
                }
                *(float2*)(tile.out + (size_t)row * tile.stride + col) = make_float2(o0, o1);
            }
        }
        __syncthreads();
    }
}

// ---------------- CSR build (once per run; edges are layer-invariant) ----------------
__global__ void zero_counts()
{
    int i = blockIdx.x * blockDim.x + threadIdx.x;
    if (i < NN) g_counts[i] = 0;
}

__device__ __forceinline__ void edge_map(int gw,
    const int* s0, const int* d0, const int* s1, const int* d1,
    const int* s2, const int* d2, const int* s3, const int* d3,
    int& kvi, int& dg)
{
    const int* sp; const int* dp; int kvoff, doff, e = gw;
    if (gw < 150000)      { sp = s0; dp = d0; kvoff = 0;      doff = 0; }
    else if (gw < 300000) { sp = s1; dp = d1; kvoff = 100000; doff = 200000; e -= 150000; }
    else if (gw < 500000) { sp = s2; dp = d2; kvoff = 300000; doff = 0;      e -= 300000; }
    else                  { sp = s3; dp = d3; kvoff = 500000; doff = 300000; e -= 500000; }
    kvi = sp[e] + kvoff;
    dg  = dp[e] + doff;
}

__global__ void hist_edges(const int* s0, const int* d0, const int* s1, const int* d1,
                           const int* s2, const int* d2, const int* s3, const int* d3)
{
    int gw = blockIdx.x * blockDim.x + threadIdx.x;
    if (gw >= E_TOT) return;
    int kvi, dg;
    edge_map(gw, s0, d0, s1, d1, s2, d2, s3, d3, kvi, dg);
    atomicAdd(&g_counts[dg], 1);
}

__global__ void scan_blocks()   // grid 342, block 1024: exclusive scan within block
{
    __shared__ int smv[1024];
    int i = blockIdx.x * 1024 + threadIdx.x;
    int v = (i < NN) ? g_counts[i] : 0;
    smv[threadIdx.x] = v;
    __syncthreads();
#pragma unroll
    for (int off = 1; off < 1024; off <<= 1) {
        int t = (threadIdx.x >= off) ? smv[threadIdx.x - off] : 0;
        __syncthreads();
        smv[threadIdx.x] += t;
        __syncthreads();
    }
    if (i < NN) g_starts[i] = smv[threadIdx.x] - v;
    if (threadIdx.x == 1023) g_bsums[blockIdx.x] = smv[1023];
}

__global__ void scan_sums(int nb)   // single block 1024
{
    __shared__ int smv[1024];
    int v = (threadIdx.x < nb) ? g_bsums[threadIdx.x] : 0;
    smv[threadIdx.x] = v;
    __syncthreads();
#pragma unroll
    for (int off = 1; off < 1024; off <<= 1) {
        int t = (threadIdx.x >= off) ? smv[threadIdx.x - off] : 0;
        __syncthreads();
        smv[threadIdx.x] += t;
        __syncthreads();
    }
    if (threadIdx.x < nb) g_boffs[threadIdx.x] = smv[threadIdx.x] - v;
}

__global__ void scan_finish()   // grid 342, block 1024
{
    int i = blockIdx.x * 1024 + threadIdx.x;
    if (i < NN) {
        int s = g_starts[i] + g_boffs[blockIdx.x];
        g_starts[i] = s;
        g_cursor[i] = s;
    }
}

__global__ void scatter_edges(const int* s0, const int* d0, const int* s1, const int* d1,
                              const int* s2, const int* d2, const int* s3, const int* d3)
{
    int gw = blockIdx.x * blockDim.x + threadIdx.x;
    if (gw >= E_TOT) return;
    int kvi, dg;
    edge_map(gw, s0, d0, s1, d1, s2, d2, s3, d3, kvi, dg);
    int pos = atomicAdd(&g_cursor[dg], 1);
    g_eidx[pos] = (unsigned int)kvi;
}

// ---------------- gather: warp per dst node, no atomics ----------------
__global__ void __launch_bounds__(256) gather_nodes(
    const float* __restrict__ KV, const float* __restrict__ Q,
    const float* __restrict__ prel, float* __restrict__ denom, float* __restrict__ agg)
{
    int n    = (blockIdx.x * blockDim.x + threadIdx.x) >> 5;
    int lane = threadIdx.x & 31;
    if (n >= NN) return;

    float4 q = *(const float4*)(Q + (size_t)n * 128 + lane * 4);
    int start = g_starts[n];
    int cnt   = g_counts[n];
    int h = lane >> 3;

    float a0 = 0.f, a1 = 0.f, a2 = 0.f, a3 = 0.f, dsum = 0.f;
    for (int j = 0; j < cnt; j++) {
        int kvi = (int)g_eidx[start + j];
        int r = (kvi < 100000) ? 0 : (kvi < 300000) ? 1 : (kvi < 500000) ? 2 : 3;
        const float* kvrow = KV + (size_t)kvi * 256;
        float4 kr = *(const float4*)(kvrow + lane * 4);
        float p = kr.x * q.x + kr.y * q.y + kr.z * q.z + kr.w * q.w;
        p += __shfl_xor_sync(0xffffffffu, p, 1);
        p += __shfl_xor_sync(0xffffffffu, p, 2);
        p += __shfl_xor_sync(0xffffffffu, p, 4);
        float a  = p * __ldg(prel + r * 4 + h) * 0.17677669529663687f;
        float ea = expf(a);
        dsum += ea;
        float4 vv = *(const float4*)(kvrow + 128 + lane * 4);
        a0 += ea * vv.x; a1 += ea * vv.y; a2 += ea * vv.z; a3 += ea * vv.w;
    }
    *(float4*)(agg + (size_t)n * 128 + lane * 4) = make_float4(a0, a1, a2, a3);
    if ((lane & 7) == 0) denom[(size_t)n * 4 + h] = dsum;
}

// ---------------- host launch ----------------
extern "C" void kernel_launch(void* const* d_in, const int* in_sizes, int n_in,
                              void* d_out, int out_size)
{
    (void)in_sizes; (void)n_in; (void)out_size;

    const float* x_in[3] = {(const float*)d_in[0], (const float*)d_in[1], (const float*)d_in[2]};
    const int* esrc[4]; const int* edst[4];
    for (int r = 0; r < 4; r++) { esrc[r] = (const int*)d_in[3 + 2*r]; edst[r] = (const int*)d_in[4 + 2*r]; }
    const float* W_in   = (const float*)d_in[11];
    const float* b_in   = (const float*)d_in[12];
    const float* Wkqv   = (const float*)d_in[13];
    const float* bkqv   = (const float*)d_in[14];
    const float* Wk_rel = (const float*)d_in[15];
    const float* Wv_rel = (const float*)d_in[16];
    const float* p_rel  = (const float*)d_in[17];
    const float* Wout   = (const float*)d_in[18];
    const float* bout   = (const float*)d_in[19];
    const float* skip   = (const float*)d_in[20];
    float* out = (float*)d_out;

    float *X, *Q, *KV, *denom, *agg, *bias;
    unsigned char* wimg;
    cudaGetSymbolAddress((void**)&X,     g_X);
    cudaGetSymbolAddress((void**)&Q,     g_Q);
    cudaGetSymbolAddress((void**)&KV,    g_KV);
    cudaGetSymbolAddress((void**)&denom, g_denom);
    cudaGetSymbolAddress((void**)&agg,   g_agg);
    cudaGetSymbolAddress((void**)&wimg,  g_wimg);
    cudaGetSymbolAddress((void**)&bias,  g_bias);

    const int SMEM = 104448;
    cudaFuncSetAttribute(gemm_multi<0>, cudaFuncAttributeMaxDynamicSharedMemorySize, SMEM);
    cudaFuncSetAttribute(gemm_multi<1>, cudaFuncAttributeMaxDynamicSharedMemorySize, SMEM);
    cudaFuncSetAttribute(gemm_multi<2>, cudaFuncAttributeMaxDynamicSharedMemorySize, SMEM);

    const int NB = (NN + 1023) / 1024;   // 342

    // ---- launch 0: plain weight preps ----
    {
        PPlainList L;
        for (int t = 0; t < 3; t++)
            L.p[t] = { W_in + (size_t)t*C*C, 128, b_in + t*128, wimg + IMG_IN(t), bias + B_IN(t) };
        for (int l = 0; l < LAYERS; l++)
            for (int t = 0; t < 3; t++) {
                L.p[3 + l*3 + t] = { Wkqv + (size_t)(l*3 + t)*C*384 + 128, 384,
                                     bkqv + (size_t)(l*3 + t)*384 + 128,
                                     wimg + IMG_Q(l,t), bias + B_Q(l,t) };
                L.p[9 + l*3 + t] = { Wout + (size_t)(l*3 + t)*C*C, 128,
                                     bout + (size_t)(l*3 + t)*128,
                                     wimg + IMG_OUT(l,t), bias + B_OUT(l,t) };
            }
        dim3 grid(64, 15);
        prep_plain_all<<<grid, 256>>>(L);
    }
    // ---- launch 1: KV weight preps ----
    {
        static const int REL_ST_L[4] = {1, 0, 0, 0};
        PKVList L;
        for (int l = 0; l < LAYERS; l++)
            for (int r = 0; r < NR; r++) {
                int st = REL_ST_L[r];
                L.p[l*4 + r] = { Wkqv + (size_t)(l*3 + st)*C*384, bkqv + (size_t)(l*3 + st)*384,
                                 Wk_rel + (size_t)(l*NR + r)*4096, Wv_rel + (size_t)(l*NR + r)*4096,
                                 wimg + IMG_KV(l,r), bias + B_KV(l,r) };
            }
        dim3 grid(128, 8);
        prep_kv_all<<<grid, 256>>>(L);
    }

    // ---- launches 2,3,4: input linear+relu (author, keyword, paper) ----
    {
        const int order[3] = {1, 2, 0};
        for (int oi = 0; oi < 3; oi++) {
            int t = order[oi];
            int M = NT_H[t];
            TileList tl; tl.n = 1;
            tl.t[0] = { wimg + IMG_IN(t), bias + B_IN(t), X + (size_t)OFFS_H[t]*C, 128, 0, 128 };
            gemm_multi<0><<<(M + 63)/64, 256, SMEM>>>(x_in[t], tl, nullptr, nullptr, nullptr, M);
        }
    }

    // ---- launch 5: layer-0 paper 7-tile GEMM (ncu profile target) ----
    for (int l = 0; l < LAYERS; l++) {
        // paper (type 0): Q + rel1,2,3 (2 col tiles each) = 7 tiles
        {
            TileList tl; tl.n = 7;
            tl.t[0] = { wimg + IMG_Q(l,0), bias + B_Q(l,0), Q + (size_t)OFFS_H[0]*C, 128, 0, 128 };
            int k = 1;
            for (int r = 1; r <= 3; r++)
                for (int c = 0; c < 2; c++)
                    tl.t[k++] = { wimg + IMG_KV(l,r), bias + B_KV(l,r) + c*128,
                                  KV + (size_t)KRELOFF_H[r]*256 + c*128, 256, c*128, 256 };
            gemm_multi<1><<<(NP + 63)/64, 256, SMEM>>>(X + (size_t)OFFS_H[0]*C, tl,
                                                       nullptr, nullptr, nullptr, NP);
        }
        // author (type 1): Q + rel0 = 3 tiles
        {
            TileList tl; tl.n = 3;
            tl.t[0] = { wimg + IMG_Q(l,1), bias + B_Q(l,1), Q + (size_t)OFFS_H[1]*C, 128, 0, 128 };
            for (int c = 0; c < 2; c++)
                tl.t[1 + c] = { wimg + IMG_KV(l,0), bias + B_KV(l,0) + c*128,
                                KV + (size_t)KRELOFF_H[0]*256 + c*128, 256, c*128, 256 };
            gemm_multi<1><<<(NA + 63)/64, 256, SMEM>>>(X + (size_t)OFFS_H[1]*C, tl,
                                                       nullptr, nullptr, nullptr, NA);
        }
        // keyword (type 2): Q only
        {
            TileList tl; tl.n = 1;
            tl.t[0] = { wimg + IMG_Q(l,2), bias + B_Q(l,2), Q + (size_t)OFFS_H[2]*C, 128, 0, 128 };
            gemm_multi<1><<<(NKW + 63)/64, 256, SMEM>>>(X + (size_t)OFFS_H[2]*C, tl,
                                                        nullptr, nullptr, nullptr, NKW);
        }

        if (l == 0) {
            // CSR build (once; independent of Q/KV but placed here to keep
            // the ncu -s 5 window on the big GEMM above)
            zero_counts<<<(NN + 255)/256, 256>>>();
            hist_edges<<<(E_TOT + 255)/256, 256>>>(esrc[0], edst[0], esrc[1], edst[1],
                                                   esrc[2], edst[2], esrc[3], edst[3]);
            scan_blocks<<<NB, 1024>>>();
            scan_sums<<<1, 1024>>>(NB);
            scan_finish<<<NB, 1024>>>();
            scatter_edges<<<(E_TOT + 255)/256, 256>>>(esrc[0], edst[0], esrc[1], edst[1],
                                                      esrc[2], edst[2], esrc[3], edst[3]);
        }

        // gather (atomic-free)
        gather_nodes<<<(NN * 32 + 255)/256, 256>>>(KV, Q, p_rel + (size_t)l*NR*H, denom, agg);

        // output projection + skip
        for (int t = 0; t < 3; t++) {
            int M = NT_H[t];
            float* Y = (l == LAYERS - 1) ? out + (size_t)OFFS_H[t]*C
                                         : X + (size_t)OFFS_H[t]*C;
            TileList tl; tl.n = 1;
            tl.t[0] = { wimg + IMG_OUT(l,t), bias + B_OUT(l,t), Y, 128, 0, 128 };
            gemm_multi<2><<<(M + 63)/64, 256, SMEM>>>(
                agg + (size_t)OFFS_H[t]*C, tl,
                X + (size_t)OFFS_H[t]*C, skip + (size_t)(l*3 + t),
                denom + (size_t)OFFS_H[t]*H, M);
        }
    }
}

// round 8
// speedup vs baseline: 2.9631x; 1.0006x over previous
#include <cuda_runtime.h>
#include <cuda_bf16.h>
#include <math.h>
#include <stdint.h>

// ---------------- problem constants ----------------
#define NP 200000
#define NA 100000
#define NKW 50000
#define NN 350000
#define C 128
#define H 4
#define D 32
#define LAYERS 2
#define NR 4
#define E_TOT 600000
#define SRC_TOT 700000   // rel0: A(100k) srcs, rel1-3: P(200k) each

static const int OFFS_H[3]     = {0, NP, NP + NA};
static const int KRELOFF_H[4]  = {0, NA, NA + NP, NA + 2*NP};
static const int NT_H[3]       = {NP, NA, NKW};

// ---------------- scratch ----------------
__device__ float g_X    [(size_t)NN * C];
__device__ float g_Q    [(size_t)NN * C];
__device__ float g_KV   [(size_t)SRC_TOT * 256];   // [Krel(128) | Vrel(128)] per (rel,node)
__device__ float g_denom[(size_t)NN * H];
__device__ float g_agg  [(size_t)NN * C];
__device__ unsigned char g_wimg[2031616];
__device__ float g_bias[3968];
// CSR (built once)
__device__ int g_counts[NN];
__device__ int g_starts[NN];
__device__ int g_cursor[NN];
__device__ int g_bsums[512];
__device__ int g_boffs[512];
__device__ unsigned int g_eidx[E_TOT];

#define IMG_IN(t)     ((size_t)(t) * 65536)
#define IMG_Q(l,t)    ((size_t)(3 + (l)*3 + (t)) * 65536)
#define IMG_OUT(l,t)  ((size_t)(9 + (l)*3 + (t)) * 65536)
#define IMG_KV(l,r)   ((size_t)15 * 65536 + (size_t)((l)*4 + (r)) * 131072)
#define B_IN(t)     ((t) * 128)
#define B_Q(l,t)    (384 + ((l)*3 + (t)) * 128)
#define B_OUT(l,t)  (1152 + ((l)*3 + (t)) * 128)
#define B_KV(l,r)   (1920 + ((l)*4 + (r)) * 256)

// ---------------- helpers ----------------
__device__ __forceinline__ uint32_t smem_to_u32(const void* p) {
    uint32_t a;
    asm("{ .reg .u64 t; cvta.to.shared.u64 t, %1; cvt.u32.u64 %0, t; }" : "=r"(a) : "l"(p));
    return a;
}
__device__ __forceinline__ float gelu_f(float x) {
    return 0.5f * x * (1.0f + erff(x * 0.70710678118654752440f));
}
__device__ __forceinline__ void ldm_x4(uint32_t* r, uint32_t a) {
    asm volatile("ldmatrix.sync.aligned.m8n8.x4.shared.b16 {%0,%1,%2,%3}, [%4];"
                 : "=r"(r[0]), "=r"(r[1]), "=r"(r[2]), "=r"(r[3]) : "r"(a));
}
__device__ __forceinline__ void ldm_x4_t(uint32_t* r, uint32_t a) {
    asm volatile("ldmatrix.sync.aligned.m8n8.x4.trans.shared.b16 {%0,%1,%2,%3}, [%4];"
                 : "=r"(r[0]), "=r"(r[1]), "=r"(r[2]), "=r"(r[3]) : "r"(a));
}
__device__ __forceinline__ void mma_bf16(float* d, const uint32_t* a, const uint32_t* b) {
    asm volatile(
        "mma.sync.aligned.m16n8k16.row.col.f32.bf16.bf16.f32 "
        "{%0,%1,%2,%3}, {%4,%5,%6,%7}, {%8,%9}, {%0,%1,%2,%3};"
        : "+f"(d[0]), "+f"(d[1]), "+f"(d[2]), "+f"(d[3])
        : "r"(a[0]), "r"(a[1]), "r"(a[2]), "r"(a[3]), "r"(b[0]), "r"(b[1]));
}

// ---------------- batched weight prep ----------------
struct PPlain { const float* W; long ldW; const float* bias; unsigned char* img; float* bOut; };
struct PPlainList { PPlain p[15]; };

__global__ void prep_plain_all(PPlainList L)
{
    const PPlain pp = L.p[blockIdx.y];
    int idx = blockIdx.x * blockDim.x + threadIdx.x;   // 0..16383
    int n = idx & 127, k = idx >> 7;
    float v = pp.W[(size_t)k * pp.ldW + n];
    uint32_t u = __float_as_uint(v);
    uint32_t hb = u & 0xFFFF0000u;
    float lo = v - __uint_as_float(hb);
    size_t off = ((size_t)k * 128 + n) * 2;
    *(unsigned short*)(pp.img + off) = (unsigned short)(hb >> 16);
    *(__nv_bfloat16*)(pp.img + 32768 + off) = __float2bfloat16(lo);
    if (k == 0) pp.bOut[n] = pp.bias[n];
}

struct PKV { const float* Wkqv; const float* bkqv; const float* Wk; const float* Wv;
             unsigned char* img; float* bOut; };
struct PKVList { PKV p[8]; };

__global__ void prep_kv_all(PKVList L)
{
    const PKV pp = L.p[blockIdx.y];
    int idx = blockIdx.x * blockDim.x + threadIdx.x;   // 0..32767
    int n = idx & 255, k = idx >> 8;
    int isV = n >> 7, nn = n & 127, h = nn >> 5, f = nn & 31;
    const float* Wr = isV ? pp.Wv : pp.Wk;
    int kqvOff = isV ? 256 : 0;
    float v = 0.f;
#pragma unroll
    for (int d = 0; d < 32; d++)
        v += pp.Wkqv[(size_t)k * 384 + kqvOff + h * 32 + d] * Wr[h * 1024 + d * 32 + f];
    uint32_t u = __float_as_uint(v);
    uint32_t hb = u & 0xFFFF0000u;
    float lo = v - __uint_as_float(hb);
    size_t off = ((size_t)k * 256 + n) * 2;
    *(unsigned short*)(pp.img + off) = (unsigned short)(hb >> 16);
    *(__nv_bfloat16*)(pp.img + 65536 + off) = __float2bfloat16(lo);
    if (k == 0) {
        float b = 0.f;
#pragma unroll
        for (int d = 0; d < 32; d++)
            b += pp.bkqv[kqvOff + h * 32 + d] * Wr[h * 1024 + d * 32 + f];
        pp.bOut[n] = b;
    }
}

// ---------------- multi-tile HMMA GEMM ----------------
struct Tile {
    const unsigned char* img;
    const float* bias;
    float* out;
    int imgNC;
    int colBase;
    int stride;
};
struct TileList { Tile t[7]; int n; };

template <int MODE>
__global__ void __launch_bounds__(256, 2) gemm_multi(
    const float* __restrict__ Ain, TileList tl,
    const float* __restrict__ Xold, const float* __restrict__ skipPtr,
    const float* __restrict__ denomPtr, int M)
{
    extern __shared__ char sm[];
    const int S = 272;
    const int A_HI = 0, A_LO = 17408, B_HI = 34816, B_LO = 69632;

    const int tid = threadIdx.x, lane = tid & 31, w = tid >> 5;
    const int rowBase = blockIdx.x * 64;
    const uint32_t smu = smem_to_u32(sm);

#pragma unroll
    for (int j = 0; j < 8; j++) {
        int f = j * 256 + tid;
        int row = f >> 5, col = (f & 31) * 4;
        float4 v = make_float4(0.f, 0.f, 0.f, 0.f);
        int gr = rowBase + row;
        if (gr < M) v = *(const float4*)(Ain + (size_t)gr * 128 + col);
        if (MODE == 2) {
            float inv = 1.f / fmaxf(denomPtr[(size_t)gr * 4 + (col >> 5)], 1e-16f);
            v.x = gelu_f(v.x * inv); v.y = gelu_f(v.y * inv);
            v.z = gelu_f(v.z * inv); v.w = gelu_f(v.w * inv);
        }
        uint32_t ux = __float_as_uint(v.x), uy = __float_as_uint(v.y);
        uint32_t uz = __float_as_uint(v.z), uw = __float_as_uint(v.w);
        uint32_t hi01 = __byte_perm(ux, uy, 0x7632);
        uint32_t hi23 = __byte_perm(uz, uw, 0x7632);
        float lx = v.x - __uint_as_float(ux & 0xFFFF0000u);
        float ly = v.y - __uint_as_float(uy & 0xFFFF0000u);
        float lz = v.z - __uint_as_float(uz & 0xFFFF0000u);
        float lw = v.w - __uint_as_float(uw & 0xFFFF0000u);
        uint32_t lo01, lo23;
        asm("cvt.rn.satfinite.bf16x2.f32 %0, %1, %2;" : "=r"(lo01) : "f"(ly), "f"(lx));
        asm("cvt.rn.satfinite.bf16x2.f32 %0, %1, %2;" : "=r"(lo23) : "f"(lw), "f"(lz));
        *(uint2*)(sm + A_HI + row * S + col * 2) = make_uint2(hi01, hi23);
        *(uint2*)(sm + A_LO + row * S + col * 2) = make_uint2(lo01, lo23);
    }

    float sg = 0.f, og = 0.f;
    if (MODE == 2) { sg = 1.f / (1.f + expf(-*skipPtr)); og = 1.f - sg; }

    const int wm = w & 3, wn = w >> 2;
    const int lr = lane & 15, lc = lane >> 4;
    const uint32_t aHi = smu + A_HI + (wm * 16 + lr) * S + lc * 16;
    const uint32_t aLo = aHi + 17408;
    const uint32_t bHiBase = smu + B_HI + lr * S + (wn * 64 + lc * 8) * 2;
    const int gid = lane >> 2, tc = (lane & 3) * 2;

    for (int ti = 0; ti < tl.n; ti++) {
        const Tile tile = tl.t[ti];

#pragma unroll
        for (int j = 0; j < 16; j++) {
            int idx = j * 256 + tid;
            int im = idx >> 11;
            int id = idx & 2047;
            int row = id >> 4, q = id & 15;
            const unsigned char* base = tile.img + (size_t)im * tile.imgNC * 256;
            uint4 v = *(const uint4*)(base + ((size_t)row * tile.imgNC + tile.colBase) * 2 + q * 16);
            *(uint4*)(sm + (im ? B_LO : B_HI) + row * S + q * 16) = v;
        }
        __syncthreads();

        float acc[8][4];
#pragma unroll
        for (int nj = 0; nj < 8; nj++)
#pragma unroll
            for (int q = 0; q < 4; q++) acc[nj][q] = 0.f;

#pragma unroll
        for (int ks = 0; ks < 8; ks++) {
            uint32_t ah[4], al[4], bh[4][4], bl[4][4];
            ldm_x4(ah, aHi + ks * 32);
            ldm_x4(al, aLo + ks * 32);
#pragma unroll
            for (int nb = 0; nb < 4; nb++) {
                ldm_x4_t(bh[nb], bHiBase + ks * 16 * S + nb * 32);
                ldm_x4_t(bl[nb], bHiBase + 34816 + ks * 16 * S + nb * 32);
            }
#pragma unroll
            for (int nj = 0; nj < 8; nj++) {
                const uint32_t* bfh = &bh[nj >> 1][(nj & 1) * 2];
                const uint32_t* bfl = &bl[nj >> 1][(nj & 1) * 2];
                mma_bf16(acc[nj], ah, bfh);
                mma_bf16(acc[nj], ah, bfl);
                mma_bf16(acc[nj], al, bfh);
            }
        }

#pragma unroll
        for (int nj = 0; nj < 8; nj++) {
            int col = wn * 64 + nj * 8 + tc;
            float b0 = __ldg(tile.bias + col), b1 = __ldg(tile.bias + col + 1);
#pragma unroll
            for (int half = 0; half < 2; half++) {
                int row = rowBase + wm * 16 + gid + half * 8;
                if (row >= M) continue;
                float o0 = acc[nj][half * 2 + 0] + b0;
                float o1 = acc[nj][half * 2 + 1] + b1;
                if (MODE == 0) {
                    o0 = fmaxf(o0, 0.f); o1 = fmaxf(o1, 0.f);
                } else if (MODE == 2) {
                    float2 xo = *(const float2*)(Xold + (size_t)row * 128 + col);
                    o0 = sg * o0 + og * xo.x;
                    o1 = sg * o1 + og * xo.y;
                }
                *(float2*)(tile.out + (size_t)row * tile.stride + col) = make_float2(o0, o1);
            }
        }
        __syncthreads();
    }
}

// ---------------- CSR build (once per run; edges are layer-invariant) ----------------
__global__ void zero_counts()
{
    int i = blockIdx.x * blockDim.x + threadIdx.x;
    if (i < NN) g_counts[i] = 0;
}

__device__ __forceinline__ void edge_map(int gw,
    const int* s0, const int* d0, const int* s1, const int* d1,
    const int* s2, const int* d2, const int* s3, const int* d3,
    int& kvi, int& dg)
{
    const int* sp; const int* dp; int kvoff, doff, e = gw;
    if (gw < 150000)      { sp = s0; dp = d0; kvoff = 0;      doff = 0; }
    else if (gw < 300000) { sp = s1; dp = d1; kvoff = 100000; doff = 200000; e -= 150000; }
    else if (gw < 500000) { sp = s2; dp = d2; kvoff = 300000; doff = 0;      e -= 300000; }
    else                  { sp = s3; dp = d3; kvoff = 500000; doff = 300000; e -= 500000; }
    kvi = sp[e] + kvoff;
    dg  = dp[e] + doff;
}

__global__ void hist_edges(const int* s0, const int* d0, const int* s1, const int* d1,
                           const int* s2, const int* d2, const int* s3, const int* d3)
{
    int gw = blockIdx.x * blockDim.x + threadIdx.x;
    if (gw >= E_TOT) return;
    int kvi, dg;
    edge_map(gw, s0, d0, s1, d1, s2, d2, s3, d3, kvi, dg);
    atomicAdd(&g_counts[dg], 1);
}

__global__ void scan_blocks()   // grid 342, block 1024: exclusive scan within block
{
    __shared__ int smv[1024];
    int i = blockIdx.x * 1024 + threadIdx.x;
    int v = (i < NN) ? g_counts[i] : 0;
    smv[threadIdx.x] = v;
    __syncthreads();
#pragma unroll
    for (int off = 1; off < 1024; off <<= 1) {
        int t = (threadIdx.x >= off) ? smv[threadIdx.x - off] : 0;
        __syncthreads();
        smv[threadIdx.x] += t;
        __syncthreads();
    }
    if (i < NN) g_starts[i] = smv[threadIdx.x] - v;
    if (threadIdx.x == 1023) g_bsums[blockIdx.x] = smv[1023];
}

__global__ void scan_sums(int nb)   // single block 1024
{
    __shared__ int smv[1024];
    int v = (threadIdx.x < nb) ? g_bsums[threadIdx.x] : 0;
    smv[threadIdx.x] = v;
    __syncthreads();
#pragma unroll
    for (int off = 1; off < 1024; off <<= 1) {
        int t = (threadIdx.x >= off) ? smv[threadIdx.x - off] : 0;
        __syncthreads();
        smv[threadIdx.x] += t;
        __syncthreads();
    }
    if (threadIdx.x < nb) g_boffs[threadIdx.x] = smv[threadIdx.x] - v;
}

__global__ void scan_finish()   // grid 342, block 1024
{
    int i = blockIdx.x * 1024 + threadIdx.x;
    if (i < NN) {
        int s = g_starts[i] + g_boffs[blockIdx.x];
        g_starts[i] = s;
        g_cursor[i] = s;
    }
}

__global__ void scatter_edges(const int* s0, const int* d0, const int* s1, const int* d1,
                              const int* s2, const int* d2, const int* s3, const int* d3)
{
    int gw = blockIdx.x * blockDim.x + threadIdx.x;
    if (gw >= E_TOT) return;
    int kvi, dg;
    edge_map(gw, s0, d0, s1, d1, s2, d2, s3, d3, kvi, dg);
    int pos = atomicAdd(&g_cursor[dg], 1);
    g_eidx[pos] = (unsigned int)kvi;
}

// ---------------- gather: warp per dst node, no atomics ----------------
__global__ void __launch_bounds__(256) gather_nodes(
    const float* __restrict__ KV, const float* __restrict__ Q,
    const float* __restrict__ prel, float* __restrict__ denom, float* __restrict__ agg)
{
    int n    = (blockIdx.x * blockDim.x + threadIdx.x) >> 5;
    int lane = threadIdx.x & 31;
    if (n >= NN) return;

    float4 q = *(const float4*)(Q + (size_t)n * 128 + lane * 4);
    int start = g_starts[n];
    int cnt   = g_counts[n];
    int h = lane >> 3;

    float a0 = 0.f, a1 = 0.f, a2 = 0.f, a3 = 0.f, dsum = 0.f;
    for (int j = 0; j < cnt; j++) {
        int kvi = (int)g_eidx[start + j];
        int r = (kvi < 100000) ? 0 : (kvi < 300000) ? 1 : (kvi < 500000) ? 2 : 3;
        const float* kvrow = KV + (size_t)kvi * 256;
        float4 kr = *(const float4*)(kvrow + lane * 4);
        float p = kr.x * q.x + kr.y * q.y + kr.z * q.z + kr.w * q.w;
        p += __shfl_xor_sync(0xffffffffu, p, 1);
        p += __shfl_xor_sync(0xffffffffu, p, 2);
        p += __shfl_xor_sync(0xffffffffu, p, 4);
        float a  = p * __ldg(prel + r * 4 + h) * 0.17677669529663687f;
        float ea = expf(a);
        dsum += ea;
        float4 vv = *(const float4*)(kvrow + 128 + lane * 4);
        a0 += ea * vv.x; a1 += ea * vv.y; a2 += ea * vv.z; a3 += ea * vv.w;
    }
    *(float4*)(agg + (size_t)n * 128 + lane * 4) = make_float4(a0, a1, a2, a3);
    if ((lane & 7) == 0) denom[(size_t)n * 4 + h] = dsum;
}

// ---------------- host launch ----------------
extern "C" void kernel_launch(void* const* d_in, const int* in_sizes, int n_in,
                              void* d_out, int out_size)
{
    (void)in_sizes; (void)n_in; (void)out_size;

    const float* x_in[3] = {(const float*)d_in[0], (const float*)d_in[1], (const float*)d_in[2]};
    const int* esrc[4]; const int* edst[4];
    for (int r = 0; r < 4; r++) { esrc[r] = (const int*)d_in[3 + 2*r]; edst[r] = (const int*)d_in[4 + 2*r]; }
    const float* W_in   = (const float*)d_in[11];
    const float* b_in   = (const float*)d_in[12];
    const float* Wkqv   = (const float*)d_in[13];
    const float* bkqv   = (const float*)d_in[14];
    const float* Wk_rel = (const float*)d_in[15];
    const float* Wv_rel = (const float*)d_in[16];
    const float* p_rel  = (const float*)d_in[17];
    const float* Wout   = (const float*)d_in[18];
    const float* bout   = (const float*)d_in[19];
    const float* skip   = (const float*)d_in[20];
    float* out = (float*)d_out;

    float *X, *Q, *KV, *denom, *agg, *bias;
    unsigned char* wimg;
    cudaGetSymbolAddress((void**)&X,     g_X);
    cudaGetSymbolAddress((void**)&Q,     g_Q);
    cudaGetSymbolAddress((void**)&KV,    g_KV);
    cudaGetSymbolAddress((void**)&denom, g_denom);
    cudaGetSymbolAddress((void**)&agg,   g_agg);
    cudaGetSymbolAddress((void**)&wimg,  g_wimg);
    cudaGetSymbolAddress((void**)&bias,  g_bias);

    const int SMEM = 104448;
    cudaFuncSetAttribute(gemm_multi<0>, cudaFuncAttributeMaxDynamicSharedMemorySize, SMEM);
    cudaFuncSetAttribute(gemm_multi<1>, cudaFuncAttributeMaxDynamicSharedMemorySize, SMEM);
    cudaFuncSetAttribute(gemm_multi<2>, cudaFuncAttributeMaxDynamicSharedMemorySize, SMEM);

    const int NB = (NN + 1023) / 1024;   // 342

    // ---- launch 0: plain weight preps ----
    {
        PPlainList L;
        for (int t = 0; t < 3; t++)
            L.p[t] = { W_in + (size_t)t*C*C, 128, b_in + t*128, wimg + IMG_IN(t), bias + B_IN(t) };
        for (int l = 0; l < LAYERS; l++)
            for (int t = 0; t < 3; t++) {
                L.p[3 + l*3 + t] = { Wkqv + (size_t)(l*3 + t)*C*384 + 128, 384,
                                     bkqv + (size_t)(l*3 + t)*384 + 128,
                                     wimg + IMG_Q(l,t), bias + B_Q(l,t) };
                L.p[9 + l*3 + t] = { Wout + (size_t)(l*3 + t)*C*C, 128,
                                     bout + (size_t)(l*3 + t)*128,
                                     wimg + IMG_OUT(l,t), bias + B_OUT(l,t) };
            }
        dim3 grid(64, 15);
        prep_plain_all<<<grid, 256>>>(L);
    }
    // ---- launch 1: KV weight preps ----
    {
        static const int REL_ST_L[4] = {1, 0, 0, 0};
        PKVList L;
        for (int l = 0; l < LAYERS; l++)
            for (int r = 0; r < NR; r++) {
                int st = REL_ST_L[r];
                L.p[l*4 + r] = { Wkqv + (size_t)(l*3 + st)*C*384, bkqv + (size_t)(l*3 + st)*384,
                                 Wk_rel + (size_t)(l*NR + r)*4096, Wv_rel + (size_t)(l*NR + r)*4096,
                                 wimg + IMG_KV(l,r), bias + B_KV(l,r) };
            }
        dim3 grid(128, 8);
        prep_kv_all<<<grid, 256>>>(L);
    }

    // ---- launches 2,3,4: input linear+relu (author, keyword, paper) ----
    {
        const int order[3] = {1, 2, 0};
        for (int oi = 0; oi < 3; oi++) {
            int t = order[oi];
            int M = NT_H[t];
            TileList tl; tl.n = 1;
            tl.t[0] = { wimg + IMG_IN(t), bias + B_IN(t), X + (size_t)OFFS_H[t]*C, 128, 0, 128 };
            gemm_multi<0><<<(M + 63)/64, 256, SMEM>>>(x_in[t], tl, nullptr, nullptr, nullptr, M);
        }
    }

    // ---- launch 5: layer-0 paper 7-tile GEMM (ncu profile target) ----
    for (int l = 0; l < LAYERS; l++) {
        // paper (type 0): Q + rel1,2,3 (2 col tiles each) = 7 tiles
        {
            TileList tl; tl.n = 7;
            tl.t[0] = { wimg + IMG_Q(l,0), bias + B_Q(l,0), Q + (size_t)OFFS_H[0]*C, 128, 0, 128 };
            int k = 1;
            for (int r = 1; r <= 3; r++)
                for (int c = 0; c < 2; c++)
                    tl.t[k++] = { wimg + IMG_KV(l,r), bias + B_KV(l,r) + c*128,
                                  KV + (size_t)KRELOFF_H[r]*256 + c*128, 256, c*128, 256 };
            gemm_multi<1><<<(NP + 63)/64, 256, SMEM>>>(X + (size_t)OFFS_H[0]*C, tl,
                                                       nullptr, nullptr, nullptr, NP);
        }
        // author (type 1): Q + rel0 = 3 tiles
        {
            TileList tl; tl.n = 3;
            tl.t[0] = { wimg + IMG_Q(l,1), bias + B_Q(l,1), Q + (size_t)OFFS_H[1]*C, 128, 0, 128 };
            for (int c = 0; c < 2; c++)
                tl.t[1 + c] = { wimg + IMG_KV(l,0), bias + B_KV(l,0) + c*128,
                                KV + (size_t)KRELOFF_H[0]*256 + c*128, 256, c*128, 256 };
            gemm_multi<1><<<(NA + 63)/64, 256, SMEM>>>(X + (size_t)OFFS_H[1]*C, tl,
                                                       nullptr, nullptr, nullptr, NA);
        }
        // keyword (type 2): Q only
        {
            TileList tl; tl.n = 1;
            tl.t[0] = { wimg + IMG_Q(l,2), bias + B_Q(l,2), Q + (size_t)OFFS_H[2]*C, 128, 0, 128 };
            gemm_multi<1><<<(NKW + 63)/64, 256, SMEM>>>(X + (size_t)OFFS_H[2]*C, tl,
                                                        nullptr, nullptr, nullptr, NKW);
        }

        if (l == 0) {
            // CSR build (once; independent of Q/KV but placed here to keep
            // the ncu -s 5 window on the big GEMM above)
            zero_counts<<<(NN + 255)/256, 256>>>();
            hist_edges<<<(E_TOT + 255)/256, 256>>>(esrc[0], edst[0], esrc[1], edst[1],
                                                   esrc[2], edst[2], esrc[3], edst[3]);
            scan_blocks<<<NB, 1024>>>();
            scan_sums<<<1, 1024>>>(NB);
            scan_finish<<<NB, 1024>>>();
            scatter_edges<<<(E_TOT + 255)/256, 256>>>(esrc[0], edst[0], esrc[1], edst[1],
                                                      esrc[2], edst[2], esrc[3], edst[3]);
        }

        // gather (atomic-free)
        gather_nodes<<<(NN * 32 + 255)/256, 256>>>(KV, Q, p_rel + (size_t)l*NR*H, denom, agg);

        // output projection + skip
        for (int t = 0; t < 3; t++) {
            int M = NT_H[t];
            float* Y = (l == LAYERS - 1) ? out + (size_t)OFFS_H[t]*C
                                         : X + (size_t)OFFS_H[t]*C;
            TileList tl; tl.n = 1;
            tl.t[0] = { wimg + IMG_OUT(l,t), bias + B_OUT(l,t), Y, 128, 0, 128 };
            gemm_multi<2><<<(M + 63)/64, 256, SMEM>>>(
                agg + (size_t)OFFS_H[t]*C, tl,
                X + (size_t)OFFS_H[t]*C, skip + (size_t)(l*3 + t),
                denom + (size_t)OFFS_H[t]*H, M);
        }
    }
}